// round 4
// baseline (speedup 1.0000x reference)
#include <cuda_runtime.h>

#define Bdim 512
#define Tdim 256
#define Fdim 1024
#define ATC  16   // T-rows per streamed chunk in attention kernel

// Scratch (no allocations allowed): 2 MB each
__device__ float g_query[Bdim * Fdim];
__device__ float g_qk[Bdim * Fdim];
__device__ float g_ctxin[Bdim * Fdim];

// ---------------------------------------------------------------------------
// Tiled fp32 GEMM with double-buffered smem: C[M,N] = A[M,K] * op(B) (+bias)
//   BNT = true : B is [N,K] row-major ("NT")
//   BNT = false: B is [K,N] row-major ("NN")
// 64x64 tile, Kc=32, 256 threads, 4x4 microtile.
// Register-prefetch pipeline: LDG chunk i+1 -> compute chunk i -> STS -> sync.
// NOTE: all SMEM stores are scalar (row stride 65 floats is NOT 16B-aligned;
// a float4 STS there traps with misaligned address).
// ---------------------------------------------------------------------------
template <bool BNT, bool HASBIAS>
__global__ __launch_bounds__(256) void gemm64v2(
    const float* __restrict__ A, const float* __restrict__ Bm,
    const float* __restrict__ bias, float* __restrict__ C,
    int M, int N, int K)
{
    __shared__ float As[2][32][65];  // [buf][k][m], padded
    __shared__ float Bs[2][32][65];  // [buf][k][n]

    const int tid = threadIdx.x;
    const int m0 = blockIdx.y * 64;
    const int n0 = blockIdx.x * 64;
    const int tx = tid & 15;
    const int ty = tid >> 4;

    // A load mapping: idx in {tid, tid+256}; row = idx>>3, kc = (idx&7)*4
    const int a_row = tid >> 3;         // 0..31 (second load: +32)
    const int a_kc  = (tid & 7) << 2;
    const float* Ap = A + (size_t)(m0 + a_row) * K + a_kc;

    // B load mapping
    const int bt_row = tid >> 3;        // NT: n-row 0..31 (+32)
    const int bt_kc  = (tid & 7) << 2;
    const int bn_kk  = tid >> 4;        // NN: k-row 0..15 (+16)
    const int bn_nc  = (tid & 15) << 2;
    const float* Bp = BNT ? (Bm + (size_t)(n0 + bt_row) * K + bt_kc)
                          : (Bm + (size_t)(bn_kk) * N + n0 + bn_nc);

    float acc[4][4];
#pragma unroll
    for (int i = 0; i < 4; i++)
#pragma unroll
        for (int j = 0; j < 4; j++) acc[i][j] = 0.f;

    float4 ra0, ra1, rb0, rb1;

    // ---- prologue: load chunk 0 ----
    ra0 = *(const float4*)(Ap);
    ra1 = *(const float4*)(Ap + (size_t)32 * K);
    if (BNT) {
        rb0 = *(const float4*)(Bp);
        rb1 = *(const float4*)(Bp + (size_t)32 * K);
    } else {
        rb0 = *(const float4*)(Bp);
        rb1 = *(const float4*)(Bp + (size_t)16 * N);
    }

    int buf = 0;
    // store chunk 0 (all scalar STS)
    {
        As[buf][a_kc + 0][a_row] = ra0.x; As[buf][a_kc + 1][a_row] = ra0.y;
        As[buf][a_kc + 2][a_row] = ra0.z; As[buf][a_kc + 3][a_row] = ra0.w;
        As[buf][a_kc + 0][a_row + 32] = ra1.x; As[buf][a_kc + 1][a_row + 32] = ra1.y;
        As[buf][a_kc + 2][a_row + 32] = ra1.z; As[buf][a_kc + 3][a_row + 32] = ra1.w;
        if (BNT) {
            Bs[buf][bt_kc + 0][bt_row] = rb0.x; Bs[buf][bt_kc + 1][bt_row] = rb0.y;
            Bs[buf][bt_kc + 2][bt_row] = rb0.z; Bs[buf][bt_kc + 3][bt_row] = rb0.w;
            Bs[buf][bt_kc + 0][bt_row + 32] = rb1.x; Bs[buf][bt_kc + 1][bt_row + 32] = rb1.y;
            Bs[buf][bt_kc + 2][bt_row + 32] = rb1.z; Bs[buf][bt_kc + 3][bt_row + 32] = rb1.w;
        } else {
            Bs[buf][bn_kk][bn_nc + 0] = rb0.x; Bs[buf][bn_kk][bn_nc + 1] = rb0.y;
            Bs[buf][bn_kk][bn_nc + 2] = rb0.z; Bs[buf][bn_kk][bn_nc + 3] = rb0.w;
            Bs[buf][bn_kk + 16][bn_nc + 0] = rb1.x; Bs[buf][bn_kk + 16][bn_nc + 1] = rb1.y;
            Bs[buf][bn_kk + 16][bn_nc + 2] = rb1.z; Bs[buf][bn_kk + 16][bn_nc + 3] = rb1.w;
        }
    }
    __syncthreads();

    for (int k0 = 32; k0 <= K; k0 += 32) {
        // prefetch next chunk (if any) into registers
        if (k0 < K) {
            const float* Apn = Ap + k0;
            ra0 = *(const float4*)(Apn);
            ra1 = *(const float4*)(Apn + (size_t)32 * K);
            if (BNT) {
                const float* Bpn = Bp + k0;
                rb0 = *(const float4*)(Bpn);
                rb1 = *(const float4*)(Bpn + (size_t)32 * K);
            } else {
                const float* Bpn = Bp + (size_t)k0 * N;
                rb0 = *(const float4*)(Bpn);
                rb1 = *(const float4*)(Bpn + (size_t)16 * N);
            }
        }

        // compute on current buffer
#pragma unroll
        for (int kk = 0; kk < 32; kk++) {
            float a0 = As[buf][kk][ty * 4 + 0], a1 = As[buf][kk][ty * 4 + 1];
            float a2 = As[buf][kk][ty * 4 + 2], a3 = As[buf][kk][ty * 4 + 3];
            float b0 = Bs[buf][kk][tx * 4 + 0], b1 = Bs[buf][kk][tx * 4 + 1];
            float b2 = Bs[buf][kk][tx * 4 + 2], b3 = Bs[buf][kk][tx * 4 + 3];
            acc[0][0] += a0 * b0; acc[0][1] += a0 * b1; acc[0][2] += a0 * b2; acc[0][3] += a0 * b3;
            acc[1][0] += a1 * b0; acc[1][1] += a1 * b1; acc[1][2] += a1 * b2; acc[1][3] += a1 * b3;
            acc[2][0] += a2 * b0; acc[2][1] += a2 * b1; acc[2][2] += a2 * b2; acc[2][3] += a2 * b3;
            acc[3][0] += a3 * b0; acc[3][1] += a3 * b1; acc[3][2] += a3 * b2; acc[3][3] += a3 * b3;
        }

        if (k0 < K) {
            int nb = buf ^ 1;
            __syncthreads();   // compute on nb (prev chunk) finished before overwrite
            As[nb][a_kc + 0][a_row] = ra0.x; As[nb][a_kc + 1][a_row] = ra0.y;
            As[nb][a_kc + 2][a_row] = ra0.z; As[nb][a_kc + 3][a_row] = ra0.w;
            As[nb][a_kc + 0][a_row + 32] = ra1.x; As[nb][a_kc + 1][a_row + 32] = ra1.y;
            As[nb][a_kc + 2][a_row + 32] = ra1.z; As[nb][a_kc + 3][a_row + 32] = ra1.w;
            if (BNT) {
                Bs[nb][bt_kc + 0][bt_row] = rb0.x; Bs[nb][bt_kc + 1][bt_row] = rb0.y;
                Bs[nb][bt_kc + 2][bt_row] = rb0.z; Bs[nb][bt_kc + 3][bt_row] = rb0.w;
                Bs[nb][bt_kc + 0][bt_row + 32] = rb1.x; Bs[nb][bt_kc + 1][bt_row + 32] = rb1.y;
                Bs[nb][bt_kc + 2][bt_row + 32] = rb1.z; Bs[nb][bt_kc + 3][bt_row + 32] = rb1.w;
            } else {
                Bs[nb][bn_kk][bn_nc + 0] = rb0.x; Bs[nb][bn_kk][bn_nc + 1] = rb0.y;
                Bs[nb][bn_kk][bn_nc + 2] = rb0.z; Bs[nb][bn_kk][bn_nc + 3] = rb0.w;
                Bs[nb][bn_kk + 16][bn_nc + 0] = rb1.x; Bs[nb][bn_kk + 16][bn_nc + 1] = rb1.y;
                Bs[nb][bn_kk + 16][bn_nc + 2] = rb1.z; Bs[nb][bn_kk + 16][bn_nc + 3] = rb1.w;
            }
            __syncthreads();
            buf = nb;
        }
    }

#pragma unroll
    for (int i = 0; i < 4; i++) {
        int row = m0 + ty * 4 + i;
#pragma unroll
        for (int j = 0; j < 4; j++) {
            int col = n0 + tx * 4 + j;
            float v = acc[i][j];
            if (HASBIAS) v += bias[col];
            C[(size_t)row * N + col] = v;
        }
    }
}

// ---------------------------------------------------------------------------
// Streaming online-softmax attention core, v2.
// One CTA per batch row b. Fused load+score: each warp owns chunk rows
// (warp, warp+8); while staging a row to SMEM it dots it against the
// register-cached qk vector. Removes the separate smem score pass.
//   scores[t] = P[b,t,:] . qk[b,:]
//   online softmax; accumulate ctx_in[b,f] = (sum_t w_t P[b,t,f]) / sum_t w_t
// ---------------------------------------------------------------------------
__global__ __launch_bounds__(256) void attn_stream(const float* __restrict__ P)
{
    extern __shared__ float sm[];
    float* Ps  = sm;                       // ATC * Fdim
    float* scs = sm + ATC * Fdim;          // ATC scores
    float* wts = scs + ATC;                // ATC weights
    float* bc  = wts + ATC;                // [0]=new max, [1]=chunk weight sum

    const int b    = blockIdx.x;
    const int tid  = threadIdx.x;          // 256
    const int lane = tid & 31;
    const int warp = tid >> 5;             // 8 warps

    const float* Pb  = P + (size_t)b * Tdim * Fdim;
    const float* qkb = g_qk + (size_t)b * Fdim;

    // lane's slice of qk for the fused dot: elements lane*4+128*j+c
    float4 qreg[8];
#pragma unroll
    for (int j = 0; j < 8; j++)
        qreg[j] = *(const float4*)(qkb + lane * 4 + 128 * j);

    const int c0 = tid * 4;                // this thread owns 4 output columns
    float4 acc = make_float4(0.f, 0.f, 0.f, 0.f);
    float m = -1e30f, s = 0.f;

    for (int t0 = 0; t0 < Tdim; t0 += ATC) {
        // ---- fused stage + score: warp w -> rows w, w+8 ----
#pragma unroll
        for (int rr = 0; rr < ATC / 8; rr++) {
            int tc = warp + rr * 8;
            const float* grow = Pb + (size_t)(t0 + tc) * Fdim;
            float* srow = Ps + tc * Fdim;
            float p = 0.f;
#pragma unroll
            for (int j = 0; j < 8; j++) {
                float4 v = *(const float4*)(grow + lane * 4 + 128 * j);
                *(float4*)(srow + lane * 4 + 128 * j) = v;
                p += v.x * qreg[j].x + v.y * qreg[j].y
                   + v.z * qreg[j].z + v.w * qreg[j].w;
            }
#pragma unroll
            for (int o = 16; o; o >>= 1) p += __shfl_xor_sync(0xffffffffu, p, o);
            if (lane == 0) scs[tc] = p;
        }
        __syncthreads();

        // ---- warp 0: chunk max, weights, weight sum ----
        if (warp == 0) {
            float sc = (lane < ATC) ? scs[lane] : -1e30f;
            float cm = sc;
#pragma unroll
            for (int o = 16; o; o >>= 1) cm = fmaxf(cm, __shfl_xor_sync(0xffffffffu, cm, o));
            float newm = fmaxf(m, cm);
            float w = (lane < ATC) ? __expf(sc - newm) : 0.f;
            if (lane < ATC) wts[lane] = w;
            float sw = w;
#pragma unroll
            for (int o = 16; o; o >>= 1) sw += __shfl_xor_sync(0xffffffffu, sw, o);
            if (lane == 0) { bc[0] = newm; bc[1] = sw; }
        }
        __syncthreads();

        // ---- rescale running state, accumulate weighted rows ----
        float newm = bc[0];
        float c = __expf(m - newm);
        s = s * c + bc[1];
        m = newm;
        acc.x *= c; acc.y *= c; acc.z *= c; acc.w *= c;
#pragma unroll
        for (int tc = 0; tc < ATC; tc++) {
            float w = wts[tc];
            float4 v = *(const float4*)(Ps + tc * Fdim + c0);
            acc.x += w * v.x; acc.y += w * v.y;
            acc.z += w * v.z; acc.w += w * v.w;
        }
        __syncthreads();   // protect Ps before next chunk's stores
    }

    float inv = 1.f / s;
    float4 o = make_float4(acc.x * inv, acc.y * inv, acc.z * inv, acc.w * inv);
    *(float4*)(g_ctxin + (size_t)b * Fdim + c0) = o;
}

// ---------------------------------------------------------------------------
// kernel_launch: query = z@Wq^T + bq ; qk = query@Wk ;
//                ctxin = softmax(P.qk)-weighted sum of P (streaming) ;
//                out = ctxin@Wv^T + bv
// ---------------------------------------------------------------------------
extern "C" void kernel_launch(void* const* d_in, const int* in_sizes, int n_in,
                              void* d_out, int out_size)
{
    const float* z  = (const float*)d_in[0];
    const float* P  = (const float*)d_in[1];
    const float* Wq = (const float*)d_in[2];
    const float* Wk = (const float*)d_in[3];
    const float* Wv = (const float*)d_in[4];
    const float* bq = (const float*)d_in[5];
    const float* bv = (const float*)d_in[7];
    float* out = (float*)d_out;

    float *query, *qk, *ctxin;
    cudaGetSymbolAddress((void**)&query, g_query);
    cudaGetSymbolAddress((void**)&qk,    g_qk);
    cudaGetSymbolAddress((void**)&ctxin, g_ctxin);

    dim3 grid(Fdim / 64, Bdim / 64);   // 16 x 8 = 128 CTAs

    // query = z @ Wq^T + bq   (Wq is [out,in] row-major -> NT)
    gemm64v2<true, true><<<grid, 256>>>(z, Wq, bq, query, Bdim, Fdim, Fdim);
    // qk = query @ Wk         (Wk is [d,f] row-major, reduce over d -> NN)
    gemm64v2<false, false><<<grid, 256>>>(query, Wk, nullptr, qk, Bdim, Fdim, Fdim);

    size_t smem = (size_t)(ATC * Fdim + ATC + ATC + 8) * sizeof(float);
    cudaFuncSetAttribute(attn_stream, cudaFuncAttributeMaxDynamicSharedMemorySize, (int)smem);
    attn_stream<<<Bdim, 256, smem>>>(P);

    // out = ctxin @ Wv^T + bv (NT)
    gemm64v2<true, true><<<grid, 256>>>(ctxin, Wv, bv, out, Bdim, Fdim, Fdim);
}

// round 6
// speedup vs baseline: 1.7067x; 1.7067x over previous
#include <cuda_runtime.h>

#define Bdim 512
#define Tdim 256
#define Fdim 1024
#define ATC  8     // T-rows per streamed chunk in attention kernel (smem 32KB -> 6 CTAs/SM)

// Scratch (no allocations allowed)
__device__ float g_query[Bdim * Fdim];
__device__ float g_qk[Bdim * Fdim];
__device__ float g_ctxin[Bdim * Fdim];
__device__ float g_p0[Bdim * Fdim];
__device__ float g_p1[Bdim * Fdim];

// ---------------------------------------------------------------------------
// Split-K tiled fp32 GEMM: Cpart[kz] = A[:, kz*K/2:(kz+1)*K/2] * op(B)slice
//   BNT = true : B is [N,K] row-major ("NT");  false: B is [K,N] ("NN")
// 64x64 tile, Kc=32, 256 threads, 4x4 microtile, single-buffered smem with
// 68-float row stride so compute-side LDS are .128 and NN stores are .128.
// grid = (N/64, M/64, 2); blockIdx.z selects K-half and output partial buffer.
// ---------------------------------------------------------------------------
template <bool BNT>
__global__ __launch_bounds__(256) void gemm_sk(
    const float* __restrict__ A, const float* __restrict__ Bm,
    float* __restrict__ P0, float* __restrict__ P1,
    int M, int N, int K)
{
    __shared__ float As[32][68];  // [k][m], 272B row stride (16B-aligned rows)
    __shared__ float Bs[32][68];  // [k][n]

    const int tid = threadIdx.x;
    const int m0 = blockIdx.y * 64;
    const int n0 = blockIdx.x * 64;
    const int kz = blockIdx.z;            // 0 or 1
    const int Kh = K >> 1;                // 512
    const int kbase = kz * Kh;
    float* C = kz ? P1 : P0;

    const int tx = tid & 15;
    const int ty = tid >> 4;

    // A load mapping: row = tid>>3 (0..31, +32), kc = (tid&7)*4
    const int a_row = tid >> 3;
    const int a_kc  = (tid & 7) << 2;
    const float* Ap = A + (size_t)(m0 + a_row) * K + kbase + a_kc;

    // B load mapping
    const int bt_row = tid >> 3;          // NT: n-row 0..31 (+32)
    const int bt_kc  = (tid & 7) << 2;
    const int bn_kk  = tid >> 4;          // NN: k-row 0..15 (+16)
    const int bn_nc  = (tid & 15) << 2;
    const float* Bp = BNT ? (Bm + (size_t)(n0 + bt_row) * K + kbase + bt_kc)
                          : (Bm + (size_t)(kbase + bn_kk) * N + n0 + bn_nc);

    float acc[4][4];
#pragma unroll
    for (int i = 0; i < 4; i++)
#pragma unroll
        for (int j = 0; j < 4; j++) acc[i][j] = 0.f;

    for (int k0 = 0; k0 < Kh; k0 += 32) {
        // ---- stage chunk ----
        {
            float4 ra0 = *(const float4*)(Ap + k0);
            float4 ra1 = *(const float4*)(Ap + k0 + (size_t)32 * K);
            // transposed scatter (scalar STS; off critical path)
            As[a_kc + 0][a_row] = ra0.x; As[a_kc + 1][a_row] = ra0.y;
            As[a_kc + 2][a_row] = ra0.z; As[a_kc + 3][a_row] = ra0.w;
            As[a_kc + 0][a_row + 32] = ra1.x; As[a_kc + 1][a_row + 32] = ra1.y;
            As[a_kc + 2][a_row + 32] = ra1.z; As[a_kc + 3][a_row + 32] = ra1.w;
            if (BNT) {
                float4 rb0 = *(const float4*)(Bp + k0);
                float4 rb1 = *(const float4*)(Bp + k0 + (size_t)32 * K);
                Bs[bt_kc + 0][bt_row] = rb0.x; Bs[bt_kc + 1][bt_row] = rb0.y;
                Bs[bt_kc + 2][bt_row] = rb0.z; Bs[bt_kc + 3][bt_row] = rb0.w;
                Bs[bt_kc + 0][bt_row + 32] = rb1.x; Bs[bt_kc + 1][bt_row + 32] = rb1.y;
                Bs[bt_kc + 2][bt_row + 32] = rb1.z; Bs[bt_kc + 3][bt_row + 32] = rb1.w;
            } else {
                const float* Bpn = Bp + (size_t)k0 * N;
                float4 rb0 = *(const float4*)(Bpn);
                float4 rb1 = *(const float4*)(Bpn + (size_t)16 * N);
                *(float4*)&Bs[bn_kk][bn_nc]      = rb0;   // stride 68 floats: 16B-aligned
                *(float4*)&Bs[bn_kk + 16][bn_nc] = rb1;
            }
        }
        __syncthreads();

        // ---- compute: 2x LDS.128 + 16 FFMA per k-step ----
#pragma unroll
        for (int kk = 0; kk < 32; kk++) {
            float4 av = *(const float4*)&As[kk][ty * 4];
            float4 bv = *(const float4*)&Bs[kk][tx * 4];
            acc[0][0] += av.x * bv.x; acc[0][1] += av.x * bv.y; acc[0][2] += av.x * bv.z; acc[0][3] += av.x * bv.w;
            acc[1][0] += av.y * bv.x; acc[1][1] += av.y * bv.y; acc[1][2] += av.y * bv.z; acc[1][3] += av.y * bv.w;
            acc[2][0] += av.z * bv.x; acc[2][1] += av.z * bv.y; acc[2][2] += av.z * bv.z; acc[2][3] += av.z * bv.w;
            acc[3][0] += av.w * bv.x; acc[3][1] += av.w * bv.y; acc[3][2] += av.w * bv.z; acc[3][3] += av.w * bv.w;
        }
        __syncthreads();
    }

#pragma unroll
    for (int i = 0; i < 4; i++) {
        int row = m0 + ty * 4 + i;
#pragma unroll
        for (int j = 0; j < 4; j++) {
            C[(size_t)row * N + n0 + tx * 4 + j] = acc[i][j];
        }
    }
}

// ---------------------------------------------------------------------------
// Deterministic split-K reduce: out = p0 + p1 (+ bias over N). float4 wide.
// ---------------------------------------------------------------------------
template <bool HASBIAS>
__global__ __launch_bounds__(256) void sk_reduce(
    const float* __restrict__ P0, const float* __restrict__ P1,
    const float* __restrict__ bias, float* __restrict__ out, int total, int N)
{
    int i = (blockIdx.x * 256 + threadIdx.x) * 4;
    if (i >= total) return;
    float4 a = *(const float4*)(P0 + i);
    float4 b = *(const float4*)(P1 + i);
    float4 r = make_float4(a.x + b.x, a.y + b.y, a.z + b.z, a.w + b.w);
    if (HASBIAS) {
        int c = i % N;   // N multiple of 4 -> all four in-row
        const float4 bb = *(const float4*)(bias + c);
        r.x += bb.x; r.y += bb.y; r.z += bb.z; r.w += bb.w;
    }
    *(float4*)(out + i) = r;
}

// ---------------------------------------------------------------------------
// Streaming online-softmax attention core.
// One CTA per batch row b, ATC=8 rows per chunk (smem ~32KB -> 6 CTAs/SM).
// Fused load+score: warp w stages row w to SMEM while dotting it against
// the register-cached qk vector.
// ---------------------------------------------------------------------------
__global__ __launch_bounds__(256) void attn_stream(const float* __restrict__ P)
{
    extern __shared__ float sm[];
    float* Ps  = sm;                       // ATC * Fdim
    float* scs = sm + ATC * Fdim;          // ATC scores
    float* wts = scs + ATC;                // ATC weights
    float* bc  = wts + ATC;                // [0]=new max, [1]=chunk weight sum

    const int b    = blockIdx.x;
    const int tid  = threadIdx.x;          // 256
    const int lane = tid & 31;
    const int warp = tid >> 5;             // 8 warps; warp w owns chunk row w

    const float* Pb  = P + (size_t)b * Tdim * Fdim;
    const float* qkb = g_qk + (size_t)b * Fdim;

    float4 qreg[8];
#pragma unroll
    for (int j = 0; j < 8; j++)
        qreg[j] = *(const float4*)(qkb + lane * 4 + 128 * j);

    const int c0 = tid * 4;
    float4 acc = make_float4(0.f, 0.f, 0.f, 0.f);
    float m = -1e30f, s = 0.f;

    for (int t0 = 0; t0 < Tdim; t0 += ATC) {
        // ---- fused stage + score: warp w -> row w ----
        {
            const float* grow = Pb + (size_t)(t0 + warp) * Fdim;
            float* srow = Ps + warp * Fdim;
            float4 v[8];
#pragma unroll
            for (int j = 0; j < 8; j++)
                v[j] = *(const float4*)(grow + lane * 4 + 128 * j);   // 8 LDG in flight
            float p = 0.f;
#pragma unroll
            for (int j = 0; j < 8; j++) {
                *(float4*)(srow + lane * 4 + 128 * j) = v[j];
                p += v[j].x * qreg[j].x + v[j].y * qreg[j].y
                   + v[j].z * qreg[j].z + v[j].w * qreg[j].w;
            }
#pragma unroll
            for (int o = 16; o; o >>= 1) p += __shfl_xor_sync(0xffffffffu, p, o);
            if (lane == 0) scs[warp] = p;
        }
        __syncthreads();

        // ---- warp 0: chunk max, weights, weight sum ----
        if (warp == 0) {
            float sc = (lane < ATC) ? scs[lane] : -1e30f;
            float cm = sc;
#pragma unroll
            for (int o = 16; o; o >>= 1) cm = fmaxf(cm, __shfl_xor_sync(0xffffffffu, cm, o));
            float newm = fmaxf(m, cm);
            float w = (lane < ATC) ? __expf(sc - newm) : 0.f;
            if (lane < ATC) wts[lane] = w;
            float sw = w;
#pragma unroll
            for (int o = 16; o; o >>= 1) sw += __shfl_xor_sync(0xffffffffu, sw, o);
            if (lane == 0) { bc[0] = newm; bc[1] = sw; }
        }
        __syncthreads();

        // ---- rescale running state, accumulate weighted rows ----
        float newm = bc[0];
        float c = __expf(m - newm);
        s = s * c + bc[1];
        m = newm;
        acc.x *= c; acc.y *= c; acc.z *= c; acc.w *= c;
#pragma unroll
        for (int tc = 0; tc < ATC; tc++) {
            float w = wts[tc];
            float4 v = *(const float4*)(Ps + tc * Fdim + c0);
            acc.x += w * v.x; acc.y += w * v.y;
            acc.z += w * v.z; acc.w += w * v.w;
        }
        __syncthreads();   // protect Ps before next chunk's stores
    }

    float inv = 1.f / s;
    float4 o = make_float4(acc.x * inv, acc.y * inv, acc.z * inv, acc.w * inv);
    *(float4*)(g_ctxin + (size_t)b * Fdim + c0) = o;
}

// ---------------------------------------------------------------------------
// kernel_launch: query = z@Wq^T + bq ; qk = query@Wk ;
//                ctxin = softmax(P.qk)-weighted sum of P (streaming) ;
//                out = ctxin@Wv^T + bv
// Each GEMM is split-K x2 (grid z) + deterministic reduce.
// ---------------------------------------------------------------------------
extern "C" void kernel_launch(void* const* d_in, const int* in_sizes, int n_in,
                              void* d_out, int out_size)
{
    const float* z  = (const float*)d_in[0];
    const float* P  = (const float*)d_in[1];
    const float* Wq = (const float*)d_in[2];
    const float* Wk = (const float*)d_in[3];
    const float* Wv = (const float*)d_in[4];
    const float* bq = (const float*)d_in[5];
    const float* bv = (const float*)d_in[7];
    float* out = (float*)d_out;

    float *query, *qk, *ctxin, *p0, *p1;
    cudaGetSymbolAddress((void**)&query, g_query);
    cudaGetSymbolAddress((void**)&qk,    g_qk);
    cudaGetSymbolAddress((void**)&ctxin, g_ctxin);
    cudaGetSymbolAddress((void**)&p0,    g_p0);
    cudaGetSymbolAddress((void**)&p1,    g_p1);

    dim3 grid(Fdim / 64, Bdim / 64, 2);       // 16 x 8 x 2 = 256 CTAs
    const int total = Bdim * Fdim;
    const int rblocks = total / 4 / 256;      // 512

    // query = z @ Wq^T + bq   (NT)
    gemm_sk<true><<<grid, 256>>>(z, Wq, p0, p1, Bdim, Fdim, Fdim);
    sk_reduce<true><<<rblocks, 256>>>(p0, p1, bq, query, total, Fdim);

    // qk = query @ Wk         (NN)
    gemm_sk<false><<<grid, 256>>>(query, Wk, p0, p1, Bdim, Fdim, Fdim);
    sk_reduce<false><<<rblocks, 256>>>(p0, p1, nullptr, qk, total, Fdim);

    // attention streaming pass
    size_t smem = (size_t)(ATC * Fdim + ATC + ATC + 8) * sizeof(float);
    cudaFuncSetAttribute(attn_stream, cudaFuncAttributeMaxDynamicSharedMemorySize, (int)smem);
    attn_stream<<<Bdim, 256, smem>>>(P);

    // out = ctxin @ Wv^T + bv (NT)
    gemm_sk<true><<<grid, 256>>>(ctxin, Wv, p0, p1, Bdim, Fdim, Fdim);
    sk_reduce<true><<<rblocks, 256>>>(p0, p1, bv, out, total, Fdim);
}

// round 9
// speedup vs baseline: 1.8995x; 1.1129x over previous
#include <cuda_runtime.h>
#include <cuda_bf16.h>
#include <mma.h>
#include <cstdint>

using namespace nvcuda;

#define Bdim 512
#define Tdim 256
#define Fdim 1024
#define ATC  8     // T-rows per streamed chunk in attention kernel

// ---------------- scratch (no allocations allowed) ----------------
__device__ __align__(16) float g_qf[Bdim * Fdim];            // query fp32 (pre-bias)
__device__ __align__(16) float g_qk[Bdim * Fdim];
__device__ __align__(16) float g_ctxin[Bdim * Fdim];
__device__ __align__(16) __nv_bfloat16 g_zh[Bdim * Fdim],  g_zl[Bdim * Fdim];
__device__ __align__(16) __nv_bfloat16 g_qh[Bdim * Fdim],  g_ql[Bdim * Fdim];
__device__ __align__(16) __nv_bfloat16 g_ch[Bdim * Fdim],  g_cl[Bdim * Fdim];
__device__ __align__(16) __nv_bfloat16 g_wqh[Fdim * Fdim], g_wql[Fdim * Fdim];
__device__ __align__(16) __nv_bfloat16 g_wkh[Fdim * Fdim], g_wkl[Fdim * Fdim]; // Wk^T split
__device__ __align__(16) __nv_bfloat16 g_wvh[Fdim * Fdim], g_wvl[Fdim * Fdim];

// ---------------- split/convert kernels ----------------
__device__ __forceinline__ void split1(float x, __nv_bfloat16& h, __nv_bfloat16& l) {
    h = __float2bfloat16(x);
    l = __float2bfloat16(x - __bfloat162float(h));
}

__global__ __launch_bounds__(256) void cvt_split(const float* __restrict__ in,
                                                 __nv_bfloat16* __restrict__ hi,
                                                 __nv_bfloat16* __restrict__ lo, int n) {
    int i = (blockIdx.x * 256 + threadIdx.x) * 4;
    if (i >= n) return;
    float4 a = *(const float4*)(in + i);
    __nv_bfloat16 h[4], l[4];
    split1(a.x, h[0], l[0]); split1(a.y, h[1], l[1]);
    split1(a.z, h[2], l[2]); split1(a.w, h[3], l[3]);
    *(uint2*)(hi + i) = *(uint2*)h;
    *(uint2*)(lo + i) = *(uint2*)l;
}

// t = in + bias[col]; split into hi/lo
__global__ __launch_bounds__(256) void cvt_bias_split(const float* __restrict__ in,
                                                      const float* __restrict__ bias,
                                                      __nv_bfloat16* __restrict__ hi,
                                                      __nv_bfloat16* __restrict__ lo,
                                                      int n, int N) {
    int i = (blockIdx.x * 256 + threadIdx.x) * 4;
    if (i >= n) return;
    float4 a = *(const float4*)(in + i);
    float4 b = *(const float4*)(bias + (i % N));
    __nv_bfloat16 h[4], l[4];
    split1(a.x + b.x, h[0], l[0]); split1(a.y + b.y, h[1], l[1]);
    split1(a.z + b.z, h[2], l[2]); split1(a.w + b.w, h[3], l[3]);
    *(uint2*)(hi + i) = *(uint2*)h;
    *(uint2*)(lo + i) = *(uint2*)l;
}

// out[n][k] = in[k][n], split into hi/lo (for Wk^T)
__global__ __launch_bounds__(256) void cvt_T_split(const float* __restrict__ in,
                                                   __nv_bfloat16* __restrict__ hi,
                                                   __nv_bfloat16* __restrict__ lo, int dim) {
    __shared__ float t[32][33];
    int bx = blockIdx.x * 32, by = blockIdx.y * 32;
    int lx = threadIdx.x & 31, ly = threadIdx.x >> 5;
#pragma unroll
    for (int r = 0; r < 4; r++)
        t[ly + r * 8][lx] = in[(size_t)(by + ly + r * 8) * dim + bx + lx];
    __syncthreads();
#pragma unroll
    for (int r = 0; r < 4; r++) {
        float v = t[lx][ly + r * 8];
        __nv_bfloat16 h, l; split1(v, h, l);
        size_t o = (size_t)(bx + ly + r * 8) * dim + by + lx;
        hi[o] = h; lo[o] = l;
    }
}

__global__ __launch_bounds__(256) void add_bias(float* __restrict__ out,
                                                const float* __restrict__ bias,
                                                int total, int N) {
    int i = (blockIdx.x * 256 + threadIdx.x) * 4;
    if (i >= total) return;
    float4 v = *(const float4*)(out + i);
    float4 b = *(const float4*)(bias + (i % N));
    v.x += b.x; v.y += b.y; v.z += b.z; v.w += b.w;
    *(float4*)(out + i) = v;
}

// ---------------------------------------------------------------------------
// Split-bf16 WMMA GEMM (NT): C_f32 = (Ah+Al)[M,K] @ (Bh+Bl)[N,K]^T
//   acc += Ah*Bh + Ah*Bl + Al*Bh   (Al*Bl dropped, ~2^-18 relative)
// BM=BN=64, BK=32, 256 threads (8 warps, warp tile 16x32), grid (N/64, M/64).
// ---------------------------------------------------------------------------
__global__ __launch_bounds__(256) void wgemm_split(
    const __nv_bfloat16* __restrict__ Ah, const __nv_bfloat16* __restrict__ Al,
    const __nv_bfloat16* __restrict__ Bh, const __nv_bfloat16* __restrict__ Bl,
    float* __restrict__ C, int M, int N, int K)
{
    __shared__ __align__(16) __nv_bfloat16 Ash[64][40], Asl[64][40];
    __shared__ __align__(16) __nv_bfloat16 Bsh[64][40], Bsl[64][40];

    const int tid = threadIdx.x;
    const int wid = tid >> 5;
    const int m0 = blockIdx.y * 64;
    const int n0 = blockIdx.x * 64;
    const int wm = wid >> 1;            // 0..3
    const int wn = wid & 1;             // 0..1

    wmma::fragment<wmma::accumulator, 16, 16, 16, float> acc[2];
    wmma::fill_fragment(acc[0], 0.f);
    wmma::fill_fragment(acc[1], 0.f);

    const int row = tid >> 2;           // 0..63
    const int seg = (tid & 3) * 8;      // 0,8,16,24
    const size_t aoff = (size_t)(m0 + row) * K + seg;
    const size_t boff = (size_t)(n0 + row) * K + seg;

    for (int k0 = 0; k0 < K; k0 += 32) {
        *(uint4*)&Ash[row][seg] = *(const uint4*)(Ah + aoff + k0);
        *(uint4*)&Asl[row][seg] = *(const uint4*)(Al + aoff + k0);
        *(uint4*)&Bsh[row][seg] = *(const uint4*)(Bh + boff + k0);
        *(uint4*)&Bsl[row][seg] = *(const uint4*)(Bl + boff + k0);
        __syncthreads();
#pragma unroll
        for (int kk = 0; kk < 32; kk += 16) {
            wmma::fragment<wmma::matrix_a, 16, 16, 16, __nv_bfloat16, wmma::row_major> afh, afl;
            wmma::load_matrix_sync(afh, &Ash[wm * 16][kk], 40);
            wmma::load_matrix_sync(afl, &Asl[wm * 16][kk], 40);
#pragma unroll
            for (int j = 0; j < 2; j++) {
                wmma::fragment<wmma::matrix_b, 16, 16, 16, __nv_bfloat16, wmma::col_major> bfh, bfl;
                wmma::load_matrix_sync(bfh, &Bsh[wn * 32 + j * 16][kk], 40);
                wmma::load_matrix_sync(bfl, &Bsl[wn * 32 + j * 16][kk], 40);
                wmma::mma_sync(acc[j], afh, bfh, acc[j]);
                wmma::mma_sync(acc[j], afh, bfl, acc[j]);
                wmma::mma_sync(acc[j], afl, bfh, acc[j]);
            }
        }
        __syncthreads();
    }

#pragma unroll
    for (int j = 0; j < 2; j++)
        wmma::store_matrix_sync(C + (size_t)(m0 + wm * 16) * N + n0 + wn * 32 + j * 16,
                                acc[j], N, wmma::mem_row_major);
}

// ---------------------------------------------------------------------------
// Streaming online-softmax attention core (unchanged from R6 WIN).
// ---------------------------------------------------------------------------
__global__ __launch_bounds__(256) void attn_stream(const float* __restrict__ P)
{
    extern __shared__ float sm[];
    float* Ps  = sm;
    float* scs = sm + ATC * Fdim;
    float* wts = scs + ATC;
    float* bc  = wts + ATC;

    const int b    = blockIdx.x;
    const int tid  = threadIdx.x;
    const int lane = tid & 31;
    const int warp = tid >> 5;

    const float* Pb  = P + (size_t)b * Tdim * Fdim;
    const float* qkb = g_qk + (size_t)b * Fdim;

    float4 qreg[8];
#pragma unroll
    for (int j = 0; j < 8; j++)
        qreg[j] = *(const float4*)(qkb + lane * 4 + 128 * j);

    const int c0 = tid * 4;
    float4 acc = make_float4(0.f, 0.f, 0.f, 0.f);
    float m = -1e30f, s = 0.f;

    for (int t0 = 0; t0 < Tdim; t0 += ATC) {
        {
            const float* grow = Pb + (size_t)(t0 + warp) * Fdim;
            float* srow = Ps + warp * Fdim;
            float4 v[8];
#pragma unroll
            for (int j = 0; j < 8; j++)
                v[j] = *(const float4*)(grow + lane * 4 + 128 * j);
            float p = 0.f;
#pragma unroll
            for (int j = 0; j < 8; j++) {
                *(float4*)(srow + lane * 4 + 128 * j) = v[j];
                p += v[j].x * qreg[j].x + v[j].y * qreg[j].y
                   + v[j].z * qreg[j].z + v[j].w * qreg[j].w;
            }
#pragma unroll
            for (int o = 16; o; o >>= 1) p += __shfl_xor_sync(0xffffffffu, p, o);
            if (lane == 0) scs[warp] = p;
        }
        __syncthreads();

        if (warp == 0) {
            float sc = (lane < ATC) ? scs[lane] : -1e30f;
            float cm = sc;
#pragma unroll
            for (int o = 16; o; o >>= 1) cm = fmaxf(cm, __shfl_xor_sync(0xffffffffu, cm, o));
            float newm = fmaxf(m, cm);
            float w = (lane < ATC) ? __expf(sc - newm) : 0.f;
            if (lane < ATC) wts[lane] = w;
            float sw = w;
#pragma unroll
            for (int o = 16; o; o >>= 1) sw += __shfl_xor_sync(0xffffffffu, sw, o);
            if (lane == 0) { bc[0] = newm; bc[1] = sw; }
        }
        __syncthreads();

        float newm = bc[0];
        float c = __expf(m - newm);
        s = s * c + bc[1];
        m = newm;
        acc.x *= c; acc.y *= c; acc.z *= c; acc.w *= c;
#pragma unroll
        for (int tc = 0; tc < ATC; tc++) {
            float w = wts[tc];
            float4 v = *(const float4*)(Ps + tc * Fdim + c0);
            acc.x += w * v.x; acc.y += w * v.y;
            acc.z += w * v.z; acc.w += w * v.w;
        }
        __syncthreads();
    }

    float inv = 1.f / s;
    float4 o = make_float4(acc.x * inv, acc.y * inv, acc.z * inv, acc.w * inv);
    *(float4*)(g_ctxin + (size_t)b * Fdim + c0) = o;
}

// ---------------------------------------------------------------------------
// kernel_launch
// ---------------------------------------------------------------------------
extern "C" void kernel_launch(void* const* d_in, const int* in_sizes, int n_in,
                              void* d_out, int out_size)
{
    const float* z  = (const float*)d_in[0];
    const float* P  = (const float*)d_in[1];
    const float* Wq = (const float*)d_in[2];
    const float* Wk = (const float*)d_in[3];
    const float* Wv = (const float*)d_in[4];
    const float* bq = (const float*)d_in[5];
    const float* bv = (const float*)d_in[7];
    float* out = (float*)d_out;

    float *qf, *qk, *ctxin;
    __nv_bfloat16 *zh, *zl, *qh, *ql, *ch, *cl, *wqh, *wql, *wkh, *wkl, *wvh, *wvl;
    cudaGetSymbolAddress((void**)&qf,    g_qf);
    cudaGetSymbolAddress((void**)&qk,    g_qk);
    cudaGetSymbolAddress((void**)&ctxin, g_ctxin);
    cudaGetSymbolAddress((void**)&zh,  g_zh);  cudaGetSymbolAddress((void**)&zl,  g_zl);
    cudaGetSymbolAddress((void**)&qh,  g_qh);  cudaGetSymbolAddress((void**)&ql,  g_ql);
    cudaGetSymbolAddress((void**)&ch,  g_ch);  cudaGetSymbolAddress((void**)&cl,  g_cl);
    cudaGetSymbolAddress((void**)&wqh, g_wqh); cudaGetSymbolAddress((void**)&wql, g_wql);
    cudaGetSymbolAddress((void**)&wkh, g_wkh); cudaGetSymbolAddress((void**)&wkl, g_wkl);
    cudaGetSymbolAddress((void**)&wvh, g_wvh); cudaGetSymbolAddress((void**)&wvl, g_wvl);

    const int total = Bdim * Fdim;
    const int wtotal = Fdim * Fdim;
    dim3 wg(Fdim / 64, Bdim / 64);        // 16 x 8 = 128 CTAs

    // ---- splits ----
    cvt_split<<<total / 1024, 256>>>(z, zh, zl, total);
    cvt_split<<<wtotal / 1024, 256>>>(Wq, wqh, wql, wtotal);
    cvt_T_split<<<dim3(Fdim / 32, Fdim / 32), 256>>>(Wk, wkh, wkl, Fdim);
    cvt_split<<<wtotal / 1024, 256>>>(Wv, wvh, wvl, wtotal);

    // ---- query_f32 = z @ Wq^T (split-bf16 WMMA) ----
    wgemm_split<<<wg, 256>>>(zh, zl, wqh, wql, qf, Bdim, Fdim, Fdim);

    // ---- (qh,ql) = split(query + bq) ----
    cvt_bias_split<<<total / 1024, 256>>>(qf, bq, qh, ql, total, Fdim);

    // ---- qk = query @ Wk  (via Wk^T, split-bf16 WMMA) ----
    wgemm_split<<<wg, 256>>>(qh, ql, wkh, wkl, qk, Bdim, Fdim, Fdim);

    // ---- attention streaming pass (fp32) ----
    size_t smem = (size_t)(ATC * Fdim + ATC + ATC + 8) * sizeof(float);
    cudaFuncSetAttribute(attn_stream, cudaFuncAttributeMaxDynamicSharedMemorySize, (int)smem);
    attn_stream<<<Bdim, 256, smem>>>(P);

    // ---- out = ctxin @ Wv^T + bv (split-bf16 WMMA + bias add) ----
    cvt_split<<<total / 1024, 256>>>(ctxin, ch, cl, total);
    wgemm_split<<<wg, 256>>>(ch, cl, wvh, wvl, out, Bdim, Fdim, Fdim);
    add_bias<<<total / 1024, 256>>>(out, bv, total, Fdim);
}

// round 11
// speedup vs baseline: 2.1096x; 1.1106x over previous
#include <cuda_runtime.h>
#include <cuda_bf16.h>
#include <mma.h>
#include <cstdint>

using namespace nvcuda;

#define Bdim 512
#define Tdim 256
#define Fdim 1024
#define ATC  8

// ---------------- scratch (no allocations allowed) ----------------
__device__ __align__(16) float g_qk[Bdim * Fdim];
__device__ __align__(16) __nv_bfloat16 g_zh[Bdim * Fdim],  g_zl[Bdim * Fdim];
__device__ __align__(16) __nv_bfloat16 g_qh[Bdim * Fdim],  g_ql[Bdim * Fdim];
__device__ __align__(16) __nv_bfloat16 g_ch[Bdim * Fdim],  g_cl[Bdim * Fdim];
__device__ __align__(16) __nv_bfloat16 g_wqh[Fdim * Fdim], g_wql[Fdim * Fdim];
__device__ __align__(16) __nv_bfloat16 g_wkh[Fdim * Fdim], g_wkl[Fdim * Fdim]; // Wk [K,N], no transpose
__device__ __align__(16) __nv_bfloat16 g_wvh[Fdim * Fdim], g_wvl[Fdim * Fdim];

__device__ __forceinline__ void split1(float x, __nv_bfloat16& h, __nv_bfloat16& l) {
    h = __float2bfloat16(x);
    l = __float2bfloat16(x - __bfloat162float(h));
}

// 8 elems/thread: 2x float4 in, 1x uint4 hi + 1x uint4 lo out
__global__ __launch_bounds__(256) void cvt_split(const float* __restrict__ in,
                                                 __nv_bfloat16* __restrict__ hi,
                                                 __nv_bfloat16* __restrict__ lo, int n) {
    int i = (blockIdx.x * 256 + threadIdx.x) * 8;
    if (i >= n) return;
    float4 a = *(const float4*)(in + i);
    float4 b = *(const float4*)(in + i + 4);
    __nv_bfloat16 h[8], l[8];
    split1(a.x, h[0], l[0]); split1(a.y, h[1], l[1]);
    split1(a.z, h[2], l[2]); split1(a.w, h[3], l[3]);
    split1(b.x, h[4], l[4]); split1(b.y, h[5], l[5]);
    split1(b.z, h[6], l[6]); split1(b.w, h[7], l[7]);
    *(uint4*)(hi + i) = *(uint4*)h;
    *(uint4*)(lo + i) = *(uint4*)l;
}

// ---------------------------------------------------------------------------
// Split-bf16 WMMA GEMM: C_f32 = (Ah+Al)[M,K] @ B, B split hi/lo.
//   BROW=0: B is [N,K] (NT, col_major frags);  BROW=1: B is [K,N] (NN, row_major frags)
//   EPI=0: store fp32 C.  EPI=1: split(C+bias) -> (Chi,Clo).  EPI=2: store C+bias fp32.
// BM=BN=64, BK=64, 256 threads (8 warps, warp tile 16x32), register prefetch,
// grid (N/64, M/64).
// ---------------------------------------------------------------------------
template <int BROW, int EPI>
__global__ __launch_bounds__(256) void wgemm_split(
    const __nv_bfloat16* __restrict__ Ah, const __nv_bfloat16* __restrict__ Al,
    const __nv_bfloat16* __restrict__ Bh, const __nv_bfloat16* __restrict__ Bl,
    const float* __restrict__ bias, float* __restrict__ Cf,
    __nv_bfloat16* __restrict__ Chi, __nv_bfloat16* __restrict__ Clo,
    int M, int N, int K)
{
    __shared__ __align__(16) char smraw[4 * 64 * 72 * 2];   // 36,864 B
    __nv_bfloat16 (*Ash)[72] = (__nv_bfloat16(*)[72])(smraw);
    __nv_bfloat16 (*Asl)[72] = (__nv_bfloat16(*)[72])(smraw + 9216);
    __nv_bfloat16 (*Bsh)[72] = (__nv_bfloat16(*)[72])(smraw + 18432);
    __nv_bfloat16 (*Bsl)[72] = (__nv_bfloat16(*)[72])(smraw + 27648);
    float* Cs = (float*)smraw;                               // 64x68 epilogue reuse

    const int tid = threadIdx.x;
    const int wid = tid >> 5;
    const int m0 = blockIdx.y * 64;
    const int n0 = blockIdx.x * 64;
    const int wm = wid >> 1;      // 0..3
    const int wn = wid & 1;       // 0..1

    wmma::fragment<wmma::accumulator, 16, 16, 16, float> acc[2];
    wmma::fill_fragment(acc[0], 0.f);
    wmma::fill_fragment(acc[1], 0.f);

    // staging map: idx in {tid, tid+256}; row = idx>>3 (0..63), seg = (idx&7)*8
    const int r0 = tid >> 3,        s0 = (tid & 7) * 8;
    const int r1 = (tid + 256) >> 3, s1 = ((tid + 256) & 7) * 8;

    const size_t aoff0 = (size_t)(m0 + r0) * K + s0;
    const size_t aoff1 = (size_t)(m0 + r1) * K + s1;
    size_t boff0, boff1, bstep;
    if (BROW == 0) { boff0 = (size_t)(n0 + r0) * K + s0; boff1 = (size_t)(n0 + r1) * K + s1; bstep = 64; }
    else           { boff0 = (size_t)r0 * N + n0 + s0;   boff1 = (size_t)r1 * N + n0 + s1;   bstep = (size_t)64 * N; }

    uint4 rah0, rah1, ral0, ral1, rbh0, rbh1, rbl0, rbl1;

    auto loadc = [&](int ck) {
        size_t ao = (size_t)ck * 64;
        size_t bo = (size_t)ck * bstep;
        rah0 = *(const uint4*)(Ah + aoff0 + ao); rah1 = *(const uint4*)(Ah + aoff1 + ao);
        ral0 = *(const uint4*)(Al + aoff0 + ao); ral1 = *(const uint4*)(Al + aoff1 + ao);
        rbh0 = *(const uint4*)(Bh + boff0 + bo); rbh1 = *(const uint4*)(Bh + boff1 + bo);
        rbl0 = *(const uint4*)(Bl + boff0 + bo); rbl1 = *(const uint4*)(Bl + boff1 + bo);
    };
    auto storec = [&]() {
        *(uint4*)&Ash[r0][s0] = rah0; *(uint4*)&Ash[r1][s1] = rah1;
        *(uint4*)&Asl[r0][s0] = ral0; *(uint4*)&Asl[r1][s1] = ral1;
        *(uint4*)&Bsh[r0][s0] = rbh0; *(uint4*)&Bsh[r1][s1] = rbh1;
        *(uint4*)&Bsl[r0][s0] = rbl0; *(uint4*)&Bsl[r1][s1] = rbl1;
    };

    const int nch = K / 64;
    loadc(0);
    storec();
    __syncthreads();

    for (int ck = 0; ck < nch; ck++) {
        if (ck + 1 < nch) loadc(ck + 1);    // prefetch behind compute

#pragma unroll
        for (int kk = 0; kk < 64; kk += 16) {
            wmma::fragment<wmma::matrix_a, 16, 16, 16, __nv_bfloat16, wmma::row_major> afh, afl;
            wmma::load_matrix_sync(afh, &Ash[wm * 16][kk], 72);
            wmma::load_matrix_sync(afl, &Asl[wm * 16][kk], 72);
#pragma unroll
            for (int j = 0; j < 2; j++) {
                if (BROW == 0) {
                    wmma::fragment<wmma::matrix_b, 16, 16, 16, __nv_bfloat16, wmma::col_major> bfh, bfl;
                    wmma::load_matrix_sync(bfh, &Bsh[wn * 32 + j * 16][kk], 72);
                    wmma::load_matrix_sync(bfl, &Bsl[wn * 32 + j * 16][kk], 72);
                    wmma::mma_sync(acc[j], afh, bfh, acc[j]);
                    wmma::mma_sync(acc[j], afh, bfl, acc[j]);
                    wmma::mma_sync(acc[j], afl, bfh, acc[j]);
                } else {
                    wmma::fragment<wmma::matrix_b, 16, 16, 16, __nv_bfloat16, wmma::row_major> bfh, bfl;
                    wmma::load_matrix_sync(bfh, &Bsh[kk][wn * 32 + j * 16], 72);
                    wmma::load_matrix_sync(bfl, &Bsl[kk][wn * 32 + j * 16], 72);
                    wmma::mma_sync(acc[j], afh, bfh, acc[j]);
                    wmma::mma_sync(acc[j], afh, bfl, acc[j]);
                    wmma::mma_sync(acc[j], afl, bfh, acc[j]);
                }
            }
        }
        __syncthreads();                    // compute done before smem overwrite
        if (ck + 1 < nch) {
            storec();
            __syncthreads();
        }
    }

    if (EPI == 0) {
#pragma unroll
        for (int j = 0; j < 2; j++)
            wmma::store_matrix_sync(Cf + (size_t)(m0 + wm * 16) * N + n0 + wn * 32 + j * 16,
                                    acc[j], N, wmma::mem_row_major);
    } else {
        // stage to smem, then vectorized bias (+split) epilogue
#pragma unroll
        for (int j = 0; j < 2; j++)
            wmma::store_matrix_sync(Cs + (size_t)(wm * 16) * 68 + wn * 32 + j * 16,
                                    acc[j], 68, wmma::mem_row_major);
        __syncthreads();
#pragma unroll
        for (int r = 0; r < 4; r++) {
            int lin = tid + r * 256;        // 0..1023
            int row = lin >> 4;             // 0..63
            int c4  = (lin & 15) * 4;       // 0..60
            float4 v = *(const float4*)&Cs[row * 68 + c4];
            float4 b = *(const float4*)(bias + n0 + c4);
            v.x += b.x; v.y += b.y; v.z += b.z; v.w += b.w;
            size_t o = (size_t)(m0 + row) * N + n0 + c4;
            if (EPI == 2) {
                *(float4*)(Cf + o) = v;
            } else {
                __nv_bfloat16 h[4], l[4];
                split1(v.x, h[0], l[0]); split1(v.y, h[1], l[1]);
                split1(v.z, h[2], l[2]); split1(v.w, h[3], l[3]);
                *(uint2*)(Chi + o) = *(uint2*)h;
                *(uint2*)(Clo + o) = *(uint2*)l;
            }
        }
    }
}

// ---------------------------------------------------------------------------
// Streaming online-softmax attention core (R6 WIN structure).
// Epilogue writes split(ctx) -> (g_ch, g_cl) directly.
// ---------------------------------------------------------------------------
__global__ __launch_bounds__(256) void attn_stream(const float* __restrict__ P)
{
    extern __shared__ float sm[];
    float* Ps  = sm;
    float* scs = sm + ATC * Fdim;
    float* wts = scs + ATC;
    float* bc  = wts + ATC;

    const int b    = blockIdx.x;
    const int tid  = threadIdx.x;
    const int lane = tid & 31;
    const int warp = tid >> 5;

    const float* Pb  = P + (size_t)b * Tdim * Fdim;
    const float* qkb = g_qk + (size_t)b * Fdim;

    float4 qreg[8];
#pragma unroll
    for (int j = 0; j < 8; j++)
        qreg[j] = *(const float4*)(qkb + lane * 4 + 128 * j);

    const int c0 = tid * 4;
    float4 acc = make_float4(0.f, 0.f, 0.f, 0.f);
    float m = -1e30f, s = 0.f;

    for (int t0 = 0; t0 < Tdim; t0 += ATC) {
        {
            const float* grow = Pb + (size_t)(t0 + warp) * Fdim;
            float* srow = Ps + warp * Fdim;
            float4 v[8];
#pragma unroll
            for (int j = 0; j < 8; j++)
                v[j] = *(const float4*)(grow + lane * 4 + 128 * j);
            float p = 0.f;
#pragma unroll
            for (int j = 0; j < 8; j++) {
                *(float4*)(srow + lane * 4 + 128 * j) = v[j];
                p += v[j].x * qreg[j].x + v[j].y * qreg[j].y
                   + v[j].z * qreg[j].z + v[j].w * qreg[j].w;
            }
#pragma unroll
            for (int o = 16; o; o >>= 1) p += __shfl_xor_sync(0xffffffffu, p, o);
            if (lane == 0) scs[warp] = p;
        }
        __syncthreads();

        if (warp == 0) {
            float sc = (lane < ATC) ? scs[lane] : -1e30f;
            float cm = sc;
#pragma unroll
            for (int o = 16; o; o >>= 1) cm = fmaxf(cm, __shfl_xor_sync(0xffffffffu, cm, o));
            float newm = fmaxf(m, cm);
            float w = (lane < ATC) ? __expf(sc - newm) : 0.f;
            if (lane < ATC) wts[lane] = w;
            float sw = w;
#pragma unroll
            for (int o = 16; o; o >>= 1) sw += __shfl_xor_sync(0xffffffffu, sw, o);
            if (lane == 0) { bc[0] = newm; bc[1] = sw; }
        }
        __syncthreads();

        float newm = bc[0];
        float c = __expf(m - newm);
        s = s * c + bc[1];
        m = newm;
        acc.x *= c; acc.y *= c; acc.z *= c; acc.w *= c;
#pragma unroll
        for (int tc = 0; tc < ATC; tc++) {
            float w = wts[tc];
            float4 v = *(const float4*)(Ps + tc * Fdim + c0);
            acc.x += w * v.x; acc.y += w * v.y;
            acc.z += w * v.z; acc.w += w * v.w;
        }
        __syncthreads();
    }

    float inv = 1.f / s;
    float4 o = make_float4(acc.x * inv, acc.y * inv, acc.z * inv, acc.w * inv);
    __nv_bfloat16 h[4], l[4];
    split1(o.x, h[0], l[0]); split1(o.y, h[1], l[1]);
    split1(o.z, h[2], l[2]); split1(o.w, h[3], l[3]);
    size_t off = (size_t)b * Fdim + c0;
    *(uint2*)(g_ch + off) = *(uint2*)h;
    *(uint2*)(g_cl + off) = *(uint2*)l;
}

// ---------------------------------------------------------------------------
// kernel_launch
// ---------------------------------------------------------------------------
extern "C" void kernel_launch(void* const* d_in, const int* in_sizes, int n_in,
                              void* d_out, int out_size)
{
    const float* z  = (const float*)d_in[0];
    const float* P  = (const float*)d_in[1];
    const float* Wq = (const float*)d_in[2];
    const float* Wk = (const float*)d_in[3];
    const float* Wv = (const float*)d_in[4];
    const float* bq = (const float*)d_in[5];
    const float* bv = (const float*)d_in[7];
    float* out = (float*)d_out;

    float *qk;
    __nv_bfloat16 *zh, *zl, *qh, *ql, *ch, *cl, *wqh, *wql, *wkh, *wkl, *wvh, *wvl;
    cudaGetSymbolAddress((void**)&qk,  g_qk);
    cudaGetSymbolAddress((void**)&zh,  g_zh);  cudaGetSymbolAddress((void**)&zl,  g_zl);
    cudaGetSymbolAddress((void**)&qh,  g_qh);  cudaGetSymbolAddress((void**)&ql,  g_ql);
    cudaGetSymbolAddress((void**)&ch,  g_ch);  cudaGetSymbolAddress((void**)&cl,  g_cl);
    cudaGetSymbolAddress((void**)&wqh, g_wqh); cudaGetSymbolAddress((void**)&wql, g_wql);
    cudaGetSymbolAddress((void**)&wkh, g_wkh); cudaGetSymbolAddress((void**)&wkl, g_wkl);
    cudaGetSymbolAddress((void**)&wvh, g_wvh); cudaGetSymbolAddress((void**)&wvl, g_wvl);

    const int total = Bdim * Fdim;
    const int wtotal = Fdim * Fdim;
    dim3 wg(Fdim / 64, Bdim / 64);        // 16 x 8 = 128 CTAs

    // ---- splits (all layouts used as-is; Wk consumed NN, no transpose) ----
    cvt_split<<<total / 2048, 256>>>(z, zh, zl, total);
    cvt_split<<<wtotal / 2048, 256>>>(Wq, wqh, wql, wtotal);
    cvt_split<<<wtotal / 2048, 256>>>(Wk, wkh, wkl, wtotal);
    cvt_split<<<wtotal / 2048, 256>>>(Wv, wvh, wvl, wtotal);

    // ---- GEMM1: (qh,ql) = split(z @ Wq^T + bq)   [NT, EPI=split+bias] ----
    wgemm_split<0, 1><<<wg, 256>>>(zh, zl, wqh, wql, bq, nullptr, qh, ql, Bdim, Fdim, Fdim);

    // ---- GEMM2: qk = query @ Wk                  [NN, EPI=plain fp32] ----
    wgemm_split<1, 0><<<wg, 256>>>(qh, ql, wkh, wkl, nullptr, qk, nullptr, nullptr, Bdim, Fdim, Fdim);

    // ---- attention streaming pass (writes ch/cl split) ----
    size_t smem = (size_t)(ATC * Fdim + ATC + ATC + 8) * sizeof(float);
    cudaFuncSetAttribute(attn_stream, cudaFuncAttributeMaxDynamicSharedMemorySize, (int)smem);
    attn_stream<<<Bdim, 256, smem>>>(P);

    // ---- GEMM3: out = ctx @ Wv^T + bv            [NT, EPI=fp32+bias] ----
    wgemm_split<0, 2><<<wg, 256>>>(ch, cl, wvh, wvl, bv, out, nullptr, nullptr, Bdim, Fdim, Fdim);
}

// round 12
// speedup vs baseline: 2.1486x; 1.0185x over previous
#include <cuda_runtime.h>
#include <cuda_bf16.h>
#include <mma.h>
#include <cstdint>

using namespace nvcuda;

#define Bdim 512
#define Tdim 256
#define Fdim 1024
#define ATC  8

// ---------------- scratch (no allocations allowed) ----------------
__device__ __align__(16) float g_qk[Bdim * Fdim];
__device__ __align__(16) __nv_bfloat16 g_zh[Bdim * Fdim],  g_zl[Bdim * Fdim];
__device__ __align__(16) __nv_bfloat16 g_qh[Bdim * Fdim],  g_ql[Bdim * Fdim];
__device__ __align__(16) __nv_bfloat16 g_ch[Bdim * Fdim],  g_cl[Bdim * Fdim];
__device__ __align__(16) __nv_bfloat16 g_wqh[Fdim * Fdim], g_wql[Fdim * Fdim];
__device__ __align__(16) __nv_bfloat16 g_wkh[Fdim * Fdim], g_wkl[Fdim * Fdim]; // Wk [K,N] (NN)
__device__ __align__(16) __nv_bfloat16 g_wvh[Fdim * Fdim], g_wvl[Fdim * Fdim];

__device__ __forceinline__ void split1(float x, __nv_bfloat16& h, __nv_bfloat16& l) {
    h = __float2bfloat16(x);
    l = __float2bfloat16(x - __bfloat162float(h));
}

// ---------------------------------------------------------------------------
// One fused split kernel for z + Wq + Wk + Wv (8 elems/thread).
// Blocks:   [0,256)   -> z      (512K elems)
//           [256,768) -> Wq     (1M elems)
//           [768,1280)-> Wk
//           [1280,1792)->Wv
// ---------------------------------------------------------------------------
__global__ __launch_bounds__(256) void cvt_split_all(
    const float* __restrict__ z,  const float* __restrict__ Wq,
    const float* __restrict__ Wk, const float* __restrict__ Wv)
{
    const float* in;
    __nv_bfloat16 *hi, *lo;
    int bid = blockIdx.x;
    if (bid < 256)       { in = z;  hi = g_zh;  lo = g_zl;  }
    else if (bid < 768)  { in = Wq; hi = g_wqh; lo = g_wql; bid -= 256; }
    else if (bid < 1280) { in = Wk; hi = g_wkh; lo = g_wkl; bid -= 768; }
    else                 { in = Wv; hi = g_wvh; lo = g_wvl; bid -= 1280; }

    int i = (bid * 256 + threadIdx.x) * 8;
    float4 a = *(const float4*)(in + i);
    float4 b = *(const float4*)(in + i + 4);
    __nv_bfloat16 h[8], l[8];
    split1(a.x, h[0], l[0]); split1(a.y, h[1], l[1]);
    split1(a.z, h[2], l[2]); split1(a.w, h[3], l[3]);
    split1(b.x, h[4], l[4]); split1(b.y, h[5], l[5]);
    split1(b.z, h[6], l[6]); split1(b.w, h[7], l[7]);
    *(uint4*)(hi + i) = *(uint4*)h;
    *(uint4*)(lo + i) = *(uint4*)l;
}

// ---------------------------------------------------------------------------
// Split-bf16 WMMA GEMM: C_f32 = (Ah+Al)[M,K] @ B, B split hi/lo.
//   BROW=0: B is [N,K] (NT, col_major frags);  BROW=1: B is [K,N] (NN, row_major)
//   EPI=0: store fp32 C.  EPI=1: split(C+bias) -> (Chi,Clo).  EPI=2: C+bias fp32.
// BM=64, BN=32, BK=64, 256 threads (8 warps as 4x2, warp tile 16x16),
// register prefetch. grid = (N/32, M/64) = 256 CTAs.
// ---------------------------------------------------------------------------
template <int BROW, int EPI>
__global__ __launch_bounds__(256) void wgemm_split(
    const __nv_bfloat16* __restrict__ Ah, const __nv_bfloat16* __restrict__ Al,
    const __nv_bfloat16* __restrict__ Bh, const __nv_bfloat16* __restrict__ Bl,
    const float* __restrict__ bias, float* __restrict__ Cf,
    __nv_bfloat16* __restrict__ Chi, __nv_bfloat16* __restrict__ Clo,
    int M, int N, int K)
{
    // A tiles: 64x72 bf16 x2 = 18432 B.  B tiles: NT 32x72 x2 = 9216; NN 64x40 x2 = 10240.
    __shared__ __align__(16) char smraw[18432 + 10240];
    const int BSTR = BROW ? 40 : 72;
    __nv_bfloat16 (*Ash)[72] = (__nv_bfloat16(*)[72])(smraw);
    __nv_bfloat16 (*Asl)[72] = (__nv_bfloat16(*)[72])(smraw + 9216);
    __nv_bfloat16* Bsh = (__nv_bfloat16*)(smraw + 18432);
    __nv_bfloat16* Bsl = Bsh + (BROW ? 64 * 40 : 32 * 72);
    float* Cs = (float*)smraw;                 // 64x40 fp32 epilogue staging (10240 B)

    const int tid = threadIdx.x;
    const int wid = tid >> 5;
    const int m0 = blockIdx.y * 64;
    const int n0 = blockIdx.x * 32;
    const int wm = wid >> 1;      // 0..3 -> m offset 16*wm
    const int wn = wid & 1;       // 0..1 -> n offset 16*wn

    wmma::fragment<wmma::accumulator, 16, 16, 16, float> acc;
    wmma::fill_fragment(acc, 0.f);

    // A staging: idx in {tid, tid+256}; row = idx>>3 (0..63), seg = (idx&7)*8
    const int ar0 = tid >> 3,         as0 = (tid & 7) * 8;
    const int ar1 = (tid + 256) >> 3, as1 = ((tid + 256) & 7) * 8;
    const size_t aoff0 = (size_t)(m0 + ar0) * K + as0;
    const size_t aoff1 = (size_t)(m0 + ar1) * K + as1;

    // B staging: one uint4 per thread per matrix
    int br, bs;
    size_t boff, bstep;
    if (BROW == 0) { br = tid >> 3; bs = (tid & 7) * 8;            // 32 rows x 8 segs
                     boff = (size_t)(n0 + br) * K + bs; bstep = 64; }
    else           { br = tid >> 2; bs = (tid & 3) * 8;            // 64 rows x 4 segs
                     boff = (size_t)br * N + n0 + bs; bstep = (size_t)64 * N; }

    uint4 rah0, rah1, ral0, ral1, rbh, rbl;

    auto loadc = [&](int ck) {
        size_t ao = (size_t)ck * 64;
        size_t bo = (size_t)ck * bstep;
        rah0 = *(const uint4*)(Ah + aoff0 + ao); rah1 = *(const uint4*)(Ah + aoff1 + ao);
        ral0 = *(const uint4*)(Al + aoff0 + ao); ral1 = *(const uint4*)(Al + aoff1 + ao);
        rbh  = *(const uint4*)(Bh + boff + bo);
        rbl  = *(const uint4*)(Bl + boff + bo);
    };
    auto storec = [&]() {
        *(uint4*)&Ash[ar0][as0] = rah0; *(uint4*)&Ash[ar1][as1] = rah1;
        *(uint4*)&Asl[ar0][as0] = ral0; *(uint4*)&Asl[ar1][as1] = ral1;
        *(uint4*)(Bsh + br * BSTR + bs) = rbh;
        *(uint4*)(Bsl + br * BSTR + bs) = rbl;
    };

    const int nch = K / 64;
    loadc(0);
    storec();
    __syncthreads();

    for (int ck = 0; ck < nch; ck++) {
        if (ck + 1 < nch) loadc(ck + 1);    // prefetch behind compute

#pragma unroll
        for (int kk = 0; kk < 64; kk += 16) {
            wmma::fragment<wmma::matrix_a, 16, 16, 16, __nv_bfloat16, wmma::row_major> afh, afl;
            wmma::load_matrix_sync(afh, &Ash[wm * 16][kk], 72);
            wmma::load_matrix_sync(afl, &Asl[wm * 16][kk], 72);
            if (BROW == 0) {
                wmma::fragment<wmma::matrix_b, 16, 16, 16, __nv_bfloat16, wmma::col_major> bfh, bfl;
                wmma::load_matrix_sync(bfh, Bsh + (wn * 16) * 72 + kk, 72);
                wmma::load_matrix_sync(bfl, Bsl + (wn * 16) * 72 + kk, 72);
                wmma::mma_sync(acc, afh, bfh, acc);
                wmma::mma_sync(acc, afh, bfl, acc);
                wmma::mma_sync(acc, afl, bfh, acc);
            } else {
                wmma::fragment<wmma::matrix_b, 16, 16, 16, __nv_bfloat16, wmma::row_major> bfh, bfl;
                wmma::load_matrix_sync(bfh, Bsh + kk * 40 + wn * 16, 40);
                wmma::load_matrix_sync(bfl, Bsl + kk * 40 + wn * 16, 40);
                wmma::mma_sync(acc, afh, bfh, acc);
                wmma::mma_sync(acc, afh, bfl, acc);
                wmma::mma_sync(acc, afl, bfh, acc);
            }
        }
        __syncthreads();                    // compute done before smem overwrite
        if (ck + 1 < nch) {
            storec();
            __syncthreads();
        }
    }

    if (EPI == 0) {
        wmma::store_matrix_sync(Cf + (size_t)(m0 + wm * 16) * N + n0 + wn * 16,
                                acc, N, wmma::mem_row_major);
    } else {
        // stage to smem (64x40 fp32), then vectorized bias (+split) epilogue
        wmma::store_matrix_sync(Cs + (size_t)(wm * 16) * 40 + wn * 16,
                                acc, 40, wmma::mem_row_major);
        __syncthreads();
#pragma unroll
        for (int r = 0; r < 2; r++) {
            int lin = tid + r * 256;        // 0..511
            int row = lin >> 3;             // 0..63
            int c4  = (lin & 7) * 4;        // 0..28
            float4 v = *(const float4*)&Cs[row * 40 + c4];
            float4 b = *(const float4*)(bias + n0 + c4);
            v.x += b.x; v.y += b.y; v.z += b.z; v.w += b.w;
            size_t o = (size_t)(m0 + row) * N + n0 + c4;
            if (EPI == 2) {
                *(float4*)(Cf + o) = v;
            } else {
                __nv_bfloat16 h[4], l[4];
                split1(v.x, h[0], l[0]); split1(v.y, h[1], l[1]);
                split1(v.z, h[2], l[2]); split1(v.w, h[3], l[3]);
                *(uint2*)(Chi + o) = *(uint2*)h;
                *(uint2*)(Clo + o) = *(uint2*)l;
            }
        }
    }
}

// ---------------------------------------------------------------------------
// Streaming online-softmax attention core (R6 WIN structure).
// Epilogue writes split(ctx) -> (g_ch, g_cl) directly.
// ---------------------------------------------------------------------------
__global__ __launch_bounds__(256) void attn_stream(const float* __restrict__ P)
{
    extern __shared__ float sm[];
    float* Ps  = sm;
    float* scs = sm + ATC * Fdim;
    float* wts = scs + ATC;
    float* bc  = wts + ATC;

    const int b    = blockIdx.x;
    const int tid  = threadIdx.x;
    const int lane = tid & 31;
    const int warp = tid >> 5;

    const float* Pb  = P + (size_t)b * Tdim * Fdim;
    const float* qkb = g_qk + (size_t)b * Fdim;

    float4 qreg[8];
#pragma unroll
    for (int j = 0; j < 8; j++)
        qreg[j] = *(const float4*)(qkb + lane * 4 + 128 * j);

    const int c0 = tid * 4;
    float4 acc = make_float4(0.f, 0.f, 0.f, 0.f);
    float m = -1e30f, s = 0.f;

    for (int t0 = 0; t0 < Tdim; t0 += ATC) {
        {
            const float* grow = Pb + (size_t)(t0 + warp) * Fdim;
            float* srow = Ps + warp * Fdim;
            float4 v[8];
#pragma unroll
            for (int j = 0; j < 8; j++)
                v[j] = *(const float4*)(grow + lane * 4 + 128 * j);
            float p = 0.f;
#pragma unroll
            for (int j = 0; j < 8; j++) {
                *(float4*)(srow + lane * 4 + 128 * j) = v[j];
                p += v[j].x * qreg[j].x + v[j].y * qreg[j].y
                   + v[j].z * qreg[j].z + v[j].w * qreg[j].w;
            }
#pragma unroll
            for (int o = 16; o; o >>= 1) p += __shfl_xor_sync(0xffffffffu, p, o);
            if (lane == 0) scs[warp] = p;
        }
        __syncthreads();

        if (warp == 0) {
            float sc = (lane < ATC) ? scs[lane] : -1e30f;
            float cm = sc;
#pragma unroll
            for (int o = 16; o; o >>= 1) cm = fmaxf(cm, __shfl_xor_sync(0xffffffffu, cm, o));
            float newm = fmaxf(m, cm);
            float w = (lane < ATC) ? __expf(sc - newm) : 0.f;
            if (lane < ATC) wts[lane] = w;
            float sw = w;
#pragma unroll
            for (int o = 16; o; o >>= 1) sw += __shfl_xor_sync(0xffffffffu, sw, o);
            if (lane == 0) { bc[0] = newm; bc[1] = sw; }
        }
        __syncthreads();

        float newm = bc[0];
        float c = __expf(m - newm);
        s = s * c + bc[1];
        m = newm;
        acc.x *= c; acc.y *= c; acc.z *= c; acc.w *= c;
#pragma unroll
        for (int tc = 0; tc < ATC; tc++) {
            float w = wts[tc];
            float4 v = *(const float4*)(Ps + tc * Fdim + c0);
            acc.x += w * v.x; acc.y += w * v.y;
            acc.z += w * v.z; acc.w += w * v.w;
        }
        __syncthreads();
    }

    float inv = 1.f / s;
    float4 o = make_float4(acc.x * inv, acc.y * inv, acc.z * inv, acc.w * inv);
    __nv_bfloat16 h[4], l[4];
    split1(o.x, h[0], l[0]); split1(o.y, h[1], l[1]);
    split1(o.z, h[2], l[2]); split1(o.w, h[3], l[3]);
    size_t off = (size_t)b * Fdim + c0;
    *(uint2*)(g_ch + off) = *(uint2*)h;
    *(uint2*)(g_cl + off) = *(uint2*)l;
}

// ---------------------------------------------------------------------------
// kernel_launch
// ---------------------------------------------------------------------------
extern "C" void kernel_launch(void* const* d_in, const int* in_sizes, int n_in,
                              void* d_out, int out_size)
{
    const float* z  = (const float*)d_in[0];
    const float* P  = (const float*)d_in[1];
    const float* Wq = (const float*)d_in[2];
    const float* Wk = (const float*)d_in[3];
    const float* Wv = (const float*)d_in[4];
    const float* bq = (const float*)d_in[5];
    const float* bv = (const float*)d_in[7];
    float* out = (float*)d_out;

    float *qk;
    __nv_bfloat16 *zh, *zl, *qh, *ql, *ch, *cl, *wqh, *wql, *wkh, *wkl, *wvh, *wvl;
    cudaGetSymbolAddress((void**)&qk,  g_qk);
    cudaGetSymbolAddress((void**)&zh,  g_zh);  cudaGetSymbolAddress((void**)&zl,  g_zl);
    cudaGetSymbolAddress((void**)&qh,  g_qh);  cudaGetSymbolAddress((void**)&ql,  g_ql);
    cudaGetSymbolAddress((void**)&ch,  g_ch);  cudaGetSymbolAddress((void**)&cl,  g_cl);
    cudaGetSymbolAddress((void**)&wqh, g_wqh); cudaGetSymbolAddress((void**)&wql, g_wql);
    cudaGetSymbolAddress((void**)&wkh, g_wkh); cudaGetSymbolAddress((void**)&wkl, g_wkl);
    cudaGetSymbolAddress((void**)&wvh, g_wvh); cudaGetSymbolAddress((void**)&wvl, g_wvl);

    // ---- one fused split pass for z + all three weights ----
    cvt_split_all<<<1792, 256>>>(z, Wq, Wk, Wv);

    dim3 wg(Fdim / 32, Bdim / 64);        // 32 x 8 = 256 CTAs

    // ---- GEMM1: (qh,ql) = split(z @ Wq^T + bq)   [NT, EPI=split+bias] ----
    wgemm_split<0, 1><<<wg, 256>>>(zh, zl, wqh, wql, bq, nullptr, qh, ql, Bdim, Fdim, Fdim);

    // ---- GEMM2: qk = query @ Wk                  [NN, EPI=plain fp32] ----
    wgemm_split<1, 0><<<wg, 256>>>(qh, ql, wkh, wkl, nullptr, qk, nullptr, nullptr, Bdim, Fdim, Fdim);

    // ---- attention streaming pass (writes ch/cl split) ----
    size_t smem = (size_t)(ATC * Fdim + ATC + ATC + 8) * sizeof(float);
    cudaFuncSetAttribute(attn_stream, cudaFuncAttributeMaxDynamicSharedMemorySize, (int)smem);
    attn_stream<<<Bdim, 256, smem>>>(P);

    // ---- GEMM3: out = ctx @ Wv^T + bv            [NT, EPI=fp32+bias] ----
    wgemm_split<0, 2><<<wg, 256>>>(ch, cl, wvh, wvl, bv, out, nullptr, nullptr, Bdim, Fdim, Fdim);
}

// round 13
// speedup vs baseline: 2.1519x; 1.0015x over previous
#include <cuda_runtime.h>
#include <cuda_bf16.h>
#include <mma.h>
#include <cstdint>

using namespace nvcuda;

#define Bdim 512
#define Tdim 256
#define Fdim 1024
#define ATC  8
#define NCH  (Tdim / ATC)   // 32 chunks

// ---------------- scratch (no allocations allowed) ----------------
__device__ __align__(16) float g_qk[Bdim * Fdim];
__device__ __align__(16) __nv_bfloat16 g_zh[Bdim * Fdim],  g_zl[Bdim * Fdim];
__device__ __align__(16) __nv_bfloat16 g_qh[Bdim * Fdim],  g_ql[Bdim * Fdim];
__device__ __align__(16) __nv_bfloat16 g_ch[Bdim * Fdim],  g_cl[Bdim * Fdim];
__device__ __align__(16) __nv_bfloat16 g_wqh[Fdim * Fdim], g_wql[Fdim * Fdim];
__device__ __align__(16) __nv_bfloat16 g_wkh[Fdim * Fdim], g_wkl[Fdim * Fdim]; // Wk [K,N] (NN)
__device__ __align__(16) __nv_bfloat16 g_wvh[Fdim * Fdim], g_wvl[Fdim * Fdim];

__device__ __forceinline__ void split1(float x, __nv_bfloat16& h, __nv_bfloat16& l) {
    h = __float2bfloat16(x);
    l = __float2bfloat16(x - __bfloat162float(h));
}

// ---------------------------------------------------------------------------
// Fused split for z + Wq + Wk + Wv (8 elems/thread).
// ---------------------------------------------------------------------------
__global__ __launch_bounds__(256) void cvt_split_all(
    const float* __restrict__ z,  const float* __restrict__ Wq,
    const float* __restrict__ Wk, const float* __restrict__ Wv)
{
    const float* in;
    __nv_bfloat16 *hi, *lo;
    int bid = blockIdx.x;
    if (bid < 256)       { in = z;  hi = g_zh;  lo = g_zl;  }
    else if (bid < 768)  { in = Wq; hi = g_wqh; lo = g_wql; bid -= 256; }
    else if (bid < 1280) { in = Wk; hi = g_wkh; lo = g_wkl; bid -= 768; }
    else                 { in = Wv; hi = g_wvh; lo = g_wvl; bid -= 1280; }

    int i = (bid * 256 + threadIdx.x) * 8;
    float4 a = *(const float4*)(in + i);
    float4 b = *(const float4*)(in + i + 4);
    __nv_bfloat16 h[8], l[8];
    split1(a.x, h[0], l[0]); split1(a.y, h[1], l[1]);
    split1(a.z, h[2], l[2]); split1(a.w, h[3], l[3]);
    split1(b.x, h[4], l[4]); split1(b.y, h[5], l[5]);
    split1(b.z, h[6], l[6]); split1(b.w, h[7], l[7]);
    *(uint4*)(hi + i) = *(uint4*)h;
    *(uint4*)(lo + i) = *(uint4*)l;
}

// ---------------------------------------------------------------------------
// Split-bf16 WMMA GEMM, double-buffered smem (1 barrier / K-chunk).
//   BROW=0: B is [N,K] (NT);  BROW=1: B is [K,N] (NN)
//   EPI=0: fp32 C.  EPI=1: split(C+bias).  EPI=2: C+bias fp32.
// BM=64, BN=32, BK=64, 256 threads (8 warps 4x2, warp tile 16x16),
// grid (N/32, M/64) = 256 CTAs. Dynamic smem ~56-57 KB.
// ---------------------------------------------------------------------------
template <int BROW, int EPI>
__global__ __launch_bounds__(256) void wgemm_split(
    const __nv_bfloat16* __restrict__ Ah, const __nv_bfloat16* __restrict__ Al,
    const __nv_bfloat16* __restrict__ Bh, const __nv_bfloat16* __restrict__ Bl,
    const float* __restrict__ bias, float* __restrict__ Cf,
    __nv_bfloat16* __restrict__ Chi, __nv_bfloat16* __restrict__ Clo,
    int M, int N, int K)
{
    extern __shared__ __align__(16) char smraw[];
    const int ABYT = 64 * 72 * 2;                 // 9216 per A matrix per buffer
    const int BSTR = BROW ? 40 : 72;
    const int BBYT = BROW ? 64 * 40 * 2 : 32 * 72 * 2;   // 5120 / 4608
    // layout: Ash[0],Ash[1],Asl[0],Asl[1],Bsh[0],Bsh[1],Bsl[0],Bsl[1]
    auto AshP = [&](int b) { return (__nv_bfloat16*)(smraw + b * ABYT); };
    auto AslP = [&](int b) { return (__nv_bfloat16*)(smraw + 2 * ABYT + b * ABYT); };
    auto BshP = [&](int b) { return (__nv_bfloat16*)(smraw + 4 * ABYT + b * BBYT); };
    auto BslP = [&](int b) { return (__nv_bfloat16*)(smraw + 4 * ABYT + 2 * BBYT + b * BBYT); };
    float* Cs = (float*)smraw;                     // 64x40 fp32 epilogue staging

    const int tid = threadIdx.x;
    const int wid = tid >> 5;
    const int m0 = blockIdx.y * 64;
    const int n0 = blockIdx.x * 32;
    const int wm = wid >> 1;      // 0..3
    const int wn = wid & 1;       // 0..1

    wmma::fragment<wmma::accumulator, 16, 16, 16, float> acc;
    wmma::fill_fragment(acc, 0.f);

    const int ar0 = tid >> 3,         as0 = (tid & 7) * 8;
    const int ar1 = (tid + 256) >> 3, as1 = ((tid + 256) & 7) * 8;
    const size_t aoff0 = (size_t)(m0 + ar0) * K + as0;
    const size_t aoff1 = (size_t)(m0 + ar1) * K + as1;

    int br, bs;
    size_t boff, bstep;
    if (BROW == 0) { br = tid >> 3; bs = (tid & 7) * 8;
                     boff = (size_t)(n0 + br) * K + bs; bstep = 64; }
    else           { br = tid >> 2; bs = (tid & 3) * 8;
                     boff = (size_t)br * N + n0 + bs; bstep = (size_t)64 * N; }

    uint4 rah0, rah1, ral0, ral1, rbh, rbl;

    auto loadc = [&](int ck) {
        size_t ao = (size_t)ck * 64;
        size_t bo = (size_t)ck * bstep;
        rah0 = *(const uint4*)(Ah + aoff0 + ao); rah1 = *(const uint4*)(Ah + aoff1 + ao);
        ral0 = *(const uint4*)(Al + aoff0 + ao); ral1 = *(const uint4*)(Al + aoff1 + ao);
        rbh  = *(const uint4*)(Bh + boff + bo);
        rbl  = *(const uint4*)(Bl + boff + bo);
    };
    auto storec = [&](int b) {
        *(uint4*)(AshP(b) + ar0 * 72 + as0) = rah0; *(uint4*)(AshP(b) + ar1 * 72 + as1) = rah1;
        *(uint4*)(AslP(b) + ar0 * 72 + as0) = ral0; *(uint4*)(AslP(b) + ar1 * 72 + as1) = ral1;
        *(uint4*)(BshP(b) + br * BSTR + bs) = rbh;
        *(uint4*)(BslP(b) + br * BSTR + bs) = rbl;
    };

    const int nch = K / 64;
    loadc(0);
    storec(0);
    __syncthreads();

    for (int ck = 0; ck < nch; ck++) {
        const int buf = ck & 1;
        if (ck + 1 < nch) loadc(ck + 1);    // prefetch behind compute

        const __nv_bfloat16* ash = AshP(buf);
        const __nv_bfloat16* asl = AslP(buf);
        const __nv_bfloat16* bsh = BshP(buf);
        const __nv_bfloat16* bsl = BslP(buf);
#pragma unroll
        for (int kk = 0; kk < 64; kk += 16) {
            wmma::fragment<wmma::matrix_a, 16, 16, 16, __nv_bfloat16, wmma::row_major> afh, afl;
            wmma::load_matrix_sync(afh, ash + (wm * 16) * 72 + kk, 72);
            wmma::load_matrix_sync(afl, asl + (wm * 16) * 72 + kk, 72);
            if (BROW == 0) {
                wmma::fragment<wmma::matrix_b, 16, 16, 16, __nv_bfloat16, wmma::col_major> bfh, bfl;
                wmma::load_matrix_sync(bfh, bsh + (wn * 16) * 72 + kk, 72);
                wmma::load_matrix_sync(bfl, bsl + (wn * 16) * 72 + kk, 72);
                wmma::mma_sync(acc, afh, bfh, acc);
                wmma::mma_sync(acc, afh, bfl, acc);
                wmma::mma_sync(acc, afl, bfh, acc);
            } else {
                wmma::fragment<wmma::matrix_b, 16, 16, 16, __nv_bfloat16, wmma::row_major> bfh, bfl;
                wmma::load_matrix_sync(bfh, bsh + kk * 40 + wn * 16, 40);
                wmma::load_matrix_sync(bfl, bsl + kk * 40 + wn * 16, 40);
                wmma::mma_sync(acc, afh, bfh, acc);
                wmma::mma_sync(acc, afh, bfl, acc);
                wmma::mma_sync(acc, afl, bfh, acc);
            }
        }
        if (ck + 1 < nch) storec(buf ^ 1);  // other buffer: no hazard with this chunk's MMA
        __syncthreads();                    // one barrier per chunk
    }

    if (EPI == 0) {
        wmma::store_matrix_sync(Cf + (size_t)(m0 + wm * 16) * N + n0 + wn * 16,
                                acc, N, wmma::mem_row_major);
    } else {
        wmma::store_matrix_sync(Cs + (size_t)(wm * 16) * 40 + wn * 16,
                                acc, 40, wmma::mem_row_major);
        __syncthreads();
#pragma unroll
        for (int r = 0; r < 2; r++) {
            int lin = tid + r * 256;
            int row = lin >> 3;             // 0..63
            int c4  = (lin & 7) * 4;        // 0..28
            float4 v = *(const float4*)&Cs[row * 40 + c4];
            float4 b = *(const float4*)(bias + n0 + c4);
            v.x += b.x; v.y += b.y; v.z += b.z; v.w += b.w;
            size_t o = (size_t)(m0 + row) * N + n0 + c4;
            if (EPI == 2) {
                *(float4*)(Cf + o) = v;
            } else {
                __nv_bfloat16 h[4], l[4];
                split1(v.x, h[0], l[0]); split1(v.y, h[1], l[1]);
                split1(v.z, h[2], l[2]); split1(v.w, h[3], l[3]);
                *(uint2*)(Chi + o) = *(uint2*)h;
                *(uint2*)(Clo + o) = *(uint2*)l;
            }
        }
    }
}

// ---------------------------------------------------------------------------
// Streaming online-softmax attention, software-pipelined.
// Double-buffered Ps; each iteration: issue next chunk's LDGs FIRST, then
// accumulate current chunk from smem (loads in flight), then STS+score,
// softmax behind one of two barriers. Epilogue writes split(ctx).
// ---------------------------------------------------------------------------
__global__ __launch_bounds__(256) void attn_stream(const float* __restrict__ P)
{
    extern __shared__ float sm[];
    float* Ps0 = sm;                          // ATC * Fdim
    float* Ps1 = sm + ATC * Fdim;             // ATC * Fdim
    float* scs = sm + 2 * ATC * Fdim;         // ATC
    float* wts = scs + ATC;                   // ATC
    float* bc  = wts + ATC;                   // 2

    const int b    = blockIdx.x;
    const int tid  = threadIdx.x;
    const int lane = tid & 31;
    const int warp = tid >> 5;                // warp w owns chunk row w

    const float* Pb  = P + (size_t)b * Tdim * Fdim;
    const float* qkb = g_qk + (size_t)b * Fdim;

    float4 qreg[8];
#pragma unroll
    for (int j = 0; j < 8; j++)
        qreg[j] = *(const float4*)(qkb + lane * 4 + 128 * j);

    const int c0 = tid * 4;
    float4 acc = make_float4(0.f, 0.f, 0.f, 0.f);
    float m = -1e30f, s = 0.f;

    // ---- prologue: chunk 0 load + stage + score ----
    {
        const float* grow = Pb + (size_t)warp * Fdim;
        float* srow = Ps0 + warp * Fdim;
        float4 v[8];
#pragma unroll
        for (int j = 0; j < 8; j++)
            v[j] = *(const float4*)(grow + lane * 4 + 128 * j);
        float p = 0.f;
#pragma unroll
        for (int j = 0; j < 8; j++) {
            *(float4*)(srow + lane * 4 + 128 * j) = v[j];
            p += v[j].x * qreg[j].x + v[j].y * qreg[j].y
               + v[j].z * qreg[j].z + v[j].w * qreg[j].w;
        }
#pragma unroll
        for (int o = 16; o; o >>= 1) p += __shfl_xor_sync(0xffffffffu, p, o);
        if (lane == 0) scs[warp] = p;
    }
    __syncthreads();
    if (warp == 0) {
        float sc = (lane < ATC) ? scs[lane] : -1e30f;
        float cm = sc;
#pragma unroll
        for (int o = 16; o; o >>= 1) cm = fmaxf(cm, __shfl_xor_sync(0xffffffffu, cm, o));
        float nm = fmaxf(m, cm);                  // m == -1e30 here
        float w = (lane < ATC) ? __expf(sc - nm) : 0.f;
        if (lane < ATC) wts[lane] = w;
        float sw = w;
#pragma unroll
        for (int o = 16; o; o >>= 1) sw += __shfl_xor_sync(0xffffffffu, sw, o);
        if (lane == 0) { bc[0] = nm; bc[1] = sw; }
    }
    __syncthreads();

    // ---- pipelined mainloop ----
    for (int ci = 0; ci < NCH; ci++) {
        float* Pcur = (ci & 1) ? Ps1 : Ps0;
        float* Pnxt = (ci & 1) ? Ps0 : Ps1;
        const bool more = (ci + 1 < NCH);

        // 1) issue next chunk's global loads (latency hidden behind step 2)
        float4 v[8];
        if (more) {
            const float* grow = Pb + (size_t)((ci + 1) * ATC + warp) * Fdim;
#pragma unroll
            for (int j = 0; j < 8; j++)
                v[j] = *(const float4*)(grow + lane * 4 + 128 * j);
        }

        // 2) rescale running state + accumulate current chunk from smem
        float newm = bc[0];
        float c = __expf(m - newm);
        s = s * c + bc[1];
        m = newm;
        acc.x *= c; acc.y *= c; acc.z *= c; acc.w *= c;
#pragma unroll
        for (int tc = 0; tc < ATC; tc++) {
            float w = wts[tc];
            float4 pv = *(const float4*)(Pcur + tc * Fdim + c0);
            acc.x += w * pv.x; acc.y += w * pv.y;
            acc.z += w * pv.z; acc.w += w * pv.w;
        }

        // 3) stage next chunk + score
        if (more) {
            float* srow = Pnxt + warp * Fdim;
            float p = 0.f;
#pragma unroll
            for (int j = 0; j < 8; j++) {
                *(float4*)(srow + lane * 4 + 128 * j) = v[j];
                p += v[j].x * qreg[j].x + v[j].y * qreg[j].y
                   + v[j].z * qreg[j].z + v[j].w * qreg[j].w;
            }
#pragma unroll
            for (int o = 16; o; o >>= 1) p += __shfl_xor_sync(0xffffffffu, p, o);
            if (lane == 0) scs[warp] = p;
        }
        __syncthreads();   // scs visible; all warps done reading wts/bc

        // 4) warp 0: softmax for next chunk
        if (more && warp == 0) {
            float sc = (lane < ATC) ? scs[lane] : -1e30f;
            float cm = sc;
#pragma unroll
            for (int o = 16; o; o >>= 1) cm = fmaxf(cm, __shfl_xor_sync(0xffffffffu, cm, o));
            float nm = fmaxf(m, cm);              // warp0's m == chunk-ci running max
            float w = (lane < ATC) ? __expf(sc - nm) : 0.f;
            if (lane < ATC) wts[lane] = w;
            float sw = w;
#pragma unroll
            for (int o = 16; o; o >>= 1) sw += __shfl_xor_sync(0xffffffffu, sw, o);
            if (lane == 0) { bc[0] = nm; bc[1] = sw; }
        }
        __syncthreads();   // wts/bc for next chunk visible
    }

    float inv = 1.f / s;
    float4 o = make_float4(acc.x * inv, acc.y * inv, acc.z * inv, acc.w * inv);
    __nv_bfloat16 h[4], l[4];
    split1(o.x, h[0], l[0]); split1(o.y, h[1], l[1]);
    split1(o.z, h[2], l[2]); split1(o.w, h[3], l[3]);
    size_t off = (size_t)b * Fdim + c0;
    *(uint2*)(g_ch + off) = *(uint2*)h;
    *(uint2*)(g_cl + off) = *(uint2*)l;
}

// ---------------------------------------------------------------------------
// kernel_launch
// ---------------------------------------------------------------------------
extern "C" void kernel_launch(void* const* d_in, const int* in_sizes, int n_in,
                              void* d_out, int out_size)
{
    const float* z  = (const float*)d_in[0];
    const float* P  = (const float*)d_in[1];
    const float* Wq = (const float*)d_in[2];
    const float* Wk = (const float*)d_in[3];
    const float* Wv = (const float*)d_in[4];
    const float* bq = (const float*)d_in[5];
    const float* bv = (const float*)d_in[7];
    float* out = (float*)d_out;

    float *qk;
    __nv_bfloat16 *zh, *zl, *qh, *ql, *ch, *cl, *wqh, *wql, *wkh, *wkl, *wvh, *wvl;
    cudaGetSymbolAddress((void**)&qk,  g_qk);
    cudaGetSymbolAddress((void**)&zh,  g_zh);  cudaGetSymbolAddress((void**)&zl,  g_zl);
    cudaGetSymbolAddress((void**)&qh,  g_qh);  cudaGetSymbolAddress((void**)&ql,  g_ql);
    cudaGetSymbolAddress((void**)&ch,  g_ch);  cudaGetSymbolAddress((void**)&cl,  g_cl);
    cudaGetSymbolAddress((void**)&wqh, g_wqh); cudaGetSymbolAddress((void**)&wql, g_wql);
    cudaGetSymbolAddress((void**)&wkh, g_wkh); cudaGetSymbolAddress((void**)&wkl, g_wkl);
    cudaGetSymbolAddress((void**)&wvh, g_wvh); cudaGetSymbolAddress((void**)&wvl, g_wvl);

    // ---- one fused split pass for z + all three weights ----
    cvt_split_all<<<1792, 256>>>(z, Wq, Wk, Wv);

    dim3 wg(Fdim / 32, Bdim / 64);        // 32 x 8 = 256 CTAs
    const int smNT = 4 * 9216 + 4 * (32 * 72 * 2);   // 55296
    const int smNN = 4 * 9216 + 4 * (64 * 40 * 2);   // 57344
    cudaFuncSetAttribute(wgemm_split<0, 1>, cudaFuncAttributeMaxDynamicSharedMemorySize, smNT);
    cudaFuncSetAttribute(wgemm_split<1, 0>, cudaFuncAttributeMaxDynamicSharedMemorySize, smNN);
    cudaFuncSetAttribute(wgemm_split<0, 2>, cudaFuncAttributeMaxDynamicSharedMemorySize, smNT);

    // ---- GEMM1: (qh,ql) = split(z @ Wq^T + bq)   [NT, EPI=split+bias] ----
    wgemm_split<0, 1><<<wg, 256, smNT>>>(zh, zl, wqh, wql, bq, nullptr, qh, ql, Bdim, Fdim, Fdim);

    // ---- GEMM2: qk = query @ Wk                  [NN, EPI=plain fp32] ----
    wgemm_split<1, 0><<<wg, 256, smNN>>>(qh, ql, wkh, wkl, nullptr, qk, nullptr, nullptr, Bdim, Fdim, Fdim);

    // ---- attention streaming pass (pipelined; writes ch/cl split) ----
    size_t smA = (size_t)(2 * ATC * Fdim + ATC + ATC + 8) * sizeof(float);
    cudaFuncSetAttribute(attn_stream, cudaFuncAttributeMaxDynamicSharedMemorySize, (int)smA);
    attn_stream<<<Bdim, 256, smA>>>(P);

    // ---- GEMM3: out = ctx @ Wv^T + bv            [NT, EPI=fp32+bias] ----
    wgemm_split<0, 2><<<wg, 256, smNT>>>(ch, cl, wvh, wvl, bv, out, nullptr, nullptr, Bdim, Fdim, Fdim);
}

// round 16
// speedup vs baseline: 2.3140x; 1.0753x over previous
#include <cuda_runtime.h>
#include <cuda_bf16.h>
#include <mma.h>
#include <cstdint>

using namespace nvcuda;

#define Bdim 512
#define Tdim 256
#define Fdim 1024
#define ATC  8

// ---------------- scratch (no allocations allowed) ----------------
__device__ __align__(16) float g_qk[Bdim * Fdim];
__device__ __align__(16) __nv_bfloat16 g_zh[Bdim * Fdim],  g_zl[Bdim * Fdim];
__device__ __align__(16) __nv_bfloat16 g_qh[Bdim * Fdim],  g_ql[Bdim * Fdim];
__device__ __align__(16) __nv_bfloat16 g_ch[Bdim * Fdim],  g_cl[Bdim * Fdim];
__device__ __align__(16) __nv_bfloat16 g_wqh[Fdim * Fdim], g_wql[Fdim * Fdim];
__device__ __align__(16) __nv_bfloat16 g_wkh[Fdim * Fdim], g_wkl[Fdim * Fdim]; // Wk [K,N] (NN)
__device__ __align__(16) __nv_bfloat16 g_wvh[Fdim * Fdim], g_wvl[Fdim * Fdim];

__device__ __forceinline__ void split1(float x, __nv_bfloat16& h, __nv_bfloat16& l) {
    h = __float2bfloat16(x);
    l = __float2bfloat16(x - __bfloat162float(h));
}

// ---------------------------------------------------------------------------
// Fused split for z + Wq + Wk + Wv (8 elems/thread).
// ---------------------------------------------------------------------------
__global__ __launch_bounds__(256) void cvt_split_all(
    const float* __restrict__ z,  const float* __restrict__ Wq,
    const float* __restrict__ Wk, const float* __restrict__ Wv)
{
    const float* in;
    __nv_bfloat16 *hi, *lo;
    int bid = blockIdx.x;
    if (bid < 256)       { in = z;  hi = g_zh;  lo = g_zl;  }
    else if (bid < 768)  { in = Wq; hi = g_wqh; lo = g_wql; bid -= 256; }
    else if (bid < 1280) { in = Wk; hi = g_wkh; lo = g_wkl; bid -= 768; }
    else                 { in = Wv; hi = g_wvh; lo = g_wvl; bid -= 1280; }

    int i = (bid * 256 + threadIdx.x) * 8;
    float4 a = *(const float4*)(in + i);
    float4 b = *(const float4*)(in + i + 4);
    __nv_bfloat16 h[8], l[8];
    split1(a.x, h[0], l[0]); split1(a.y, h[1], l[1]);
    split1(a.z, h[2], l[2]); split1(a.w, h[3], l[3]);
    split1(b.x, h[4], l[4]); split1(b.y, h[5], l[5]);
    split1(b.z, h[6], l[6]); split1(b.w, h[7], l[7]);
    *(uint4*)(hi + i) = *(uint4*)h;
    *(uint4*)(lo + i) = *(uint4*)l;
}

// ---------------------------------------------------------------------------
// Split-bf16 WMMA GEMM, double-buffered smem (1 barrier / K-chunk). (R13)
// ---------------------------------------------------------------------------
template <int BROW, int EPI>
__global__ __launch_bounds__(256) void wgemm_split(
    const __nv_bfloat16* __restrict__ Ah, const __nv_bfloat16* __restrict__ Al,
    const __nv_bfloat16* __restrict__ Bh, const __nv_bfloat16* __restrict__ Bl,
    const float* __restrict__ bias, float* __restrict__ Cf,
    __nv_bfloat16* __restrict__ Chi, __nv_bfloat16* __restrict__ Clo,
    int M, int N, int K)
{
    extern __shared__ __align__(16) char smraw[];
    const int ABYT = 64 * 72 * 2;
    const int BSTR = BROW ? 40 : 72;
    const int BBYT = BROW ? 64 * 40 * 2 : 32 * 72 * 2;
    auto AshP = [&](int b) { return (__nv_bfloat16*)(smraw + b * ABYT); };
    auto AslP = [&](int b) { return (__nv_bfloat16*)(smraw + 2 * ABYT + b * ABYT); };
    auto BshP = [&](int b) { return (__nv_bfloat16*)(smraw + 4 * ABYT + b * BBYT); };
    auto BslP = [&](int b) { return (__nv_bfloat16*)(smraw + 4 * ABYT + 2 * BBYT + b * BBYT); };
    float* Cs = (float*)smraw;

    const int tid = threadIdx.x;
    const int wid = tid >> 5;
    const int m0 = blockIdx.y * 64;
    const int n0 = blockIdx.x * 32;
    const int wm = wid >> 1;
    const int wn = wid & 1;

    wmma::fragment<wmma::accumulator, 16, 16, 16, float> acc;
    wmma::fill_fragment(acc, 0.f);

    const int ar0 = tid >> 3,         as0 = (tid & 7) * 8;
    const int ar1 = (tid + 256) >> 3, as1 = ((tid + 256) & 7) * 8;
    const size_t aoff0 = (size_t)(m0 + ar0) * K + as0;
    const size_t aoff1 = (size_t)(m0 + ar1) * K + as1;

    int br, bs;
    size_t boff, bstep;
    if (BROW == 0) { br = tid >> 3; bs = (tid & 7) * 8;
                     boff = (size_t)(n0 + br) * K + bs; bstep = 64; }
    else           { br = tid >> 2; bs = (tid & 3) * 8;
                     boff = (size_t)br * N + n0 + bs; bstep = (size_t)64 * N; }

    uint4 rah0, rah1, ral0, ral1, rbh, rbl;

    auto loadc = [&](int ck) {
        size_t ao = (size_t)ck * 64;
        size_t bo = (size_t)ck * bstep;
        rah0 = *(const uint4*)(Ah + aoff0 + ao); rah1 = *(const uint4*)(Ah + aoff1 + ao);
        ral0 = *(const uint4*)(Al + aoff0 + ao); ral1 = *(const uint4*)(Al + aoff1 + ao);
        rbh  = *(const uint4*)(Bh + boff + bo);
        rbl  = *(const uint4*)(Bl + boff + bo);
    };
    auto storec = [&](int b) {
        *(uint4*)(AshP(b) + ar0 * 72 + as0) = rah0; *(uint4*)(AshP(b) + ar1 * 72 + as1) = rah1;
        *(uint4*)(AslP(b) + ar0 * 72 + as0) = ral0; *(uint4*)(AslP(b) + ar1 * 72 + as1) = ral1;
        *(uint4*)(BshP(b) + br * BSTR + bs) = rbh;
        *(uint4*)(BslP(b) + br * BSTR + bs) = rbl;
    };

    const int nch = K / 64;
    loadc(0);
    storec(0);
    __syncthreads();

    for (int ck = 0; ck < nch; ck++) {
        const int buf = ck & 1;
        if (ck + 1 < nch) loadc(ck + 1);

        const __nv_bfloat16* ash = AshP(buf);
        const __nv_bfloat16* asl = AslP(buf);
        const __nv_bfloat16* bsh = BshP(buf);
        const __nv_bfloat16* bsl = BslP(buf);
#pragma unroll
        for (int kk = 0; kk < 64; kk += 16) {
            wmma::fragment<wmma::matrix_a, 16, 16, 16, __nv_bfloat16, wmma::row_major> afh, afl;
            wmma::load_matrix_sync(afh, ash + (wm * 16) * 72 + kk, 72);
            wmma::load_matrix_sync(afl, asl + (wm * 16) * 72 + kk, 72);
            if (BROW == 0) {
                wmma::fragment<wmma::matrix_b, 16, 16, 16, __nv_bfloat16, wmma::col_major> bfh, bfl;
                wmma::load_matrix_sync(bfh, bsh + (wn * 16) * 72 + kk, 72);
                wmma::load_matrix_sync(bfl, bsl + (wn * 16) * 72 + kk, 72);
                wmma::mma_sync(acc, afh, bfh, acc);
                wmma::mma_sync(acc, afh, bfl, acc);
                wmma::mma_sync(acc, afl, bfh, acc);
            } else {
                wmma::fragment<wmma::matrix_b, 16, 16, 16, __nv_bfloat16, wmma::row_major> bfh, bfl;
                wmma::load_matrix_sync(bfh, bsh + kk * 40 + wn * 16, 40);
                wmma::load_matrix_sync(bfl, bsl + kk * 40 + wn * 16, 40);
                wmma::mma_sync(acc, afh, bfh, acc);
                wmma::mma_sync(acc, afh, bfl, acc);
                wmma::mma_sync(acc, afl, bfh, acc);
            }
        }
        if (ck + 1 < nch) storec(buf ^ 1);
        __syncthreads();
    }

    if (EPI == 0) {
        wmma::store_matrix_sync(Cf + (size_t)(m0 + wm * 16) * N + n0 + wn * 16,
                                acc, N, wmma::mem_row_major);
    } else {
        wmma::store_matrix_sync(Cs + (size_t)(wm * 16) * 40 + wn * 16,
                                acc, 40, wmma::mem_row_major);
        __syncthreads();
#pragma unroll
        for (int r = 0; r < 2; r++) {
            int lin = tid + r * 256;
            int row = lin >> 3;
            int c4  = (lin & 7) * 4;
            float4 v = *(const float4*)&Cs[row * 40 + c4];
            float4 b = *(const float4*)(bias + n0 + c4);
            v.x += b.x; v.y += b.y; v.z += b.z; v.w += b.w;
            size_t o = (size_t)(m0 + row) * N + n0 + c4;
            if (EPI == 2) {
                *(float4*)(Cf + o) = v;
            } else {
                __nv_bfloat16 h[4], l[4];
                split1(v.x, h[0], l[0]); split1(v.y, h[1], l[1]);
                split1(v.z, h[2], l[2]); split1(v.w, h[3], l[3]);
                *(uint2*)(Chi + o) = *(uint2*)h;
                *(uint2*)(Clo + o) = *(uint2*)l;
            }
        }
    }
}

// ---------------------------------------------------------------------------
// Attention v3: unified column mapping, no smem data staging.
// Thread t owns columns [4t,4t+4) for BOTH score partials and accumulation.
// Per chunk of 8 rows: 8 coalesced LDG.128/thread -> register v[8];
// score partials vs qk[c0..c0+3] (4 regs), warp butterfly + cross-warp smem
// reduce; accumulate from the SAME registers. 2 barriers/chunk, ~0 smem.
// Epilogue writes split(ctx) -> (g_ch, g_cl).
// ---------------------------------------------------------------------------
__global__ __launch_bounds__(256, 4) void attn_stream(const float* __restrict__ P)
{
    __shared__ float scs[64];   // 8 warps x 8 rows (per-warp partial sums)
    __shared__ float wts[ATC];
    __shared__ float bc[2];     // [0]=new max, [1]=chunk weight sum

    const int b    = blockIdx.x;
    const int tid  = threadIdx.x;
    const int lane = tid & 31;
    const int warp = tid >> 5;
    const int c0   = tid * 4;

    const float* Pb = P + (size_t)b * Tdim * Fdim;
    const float4 q4 = *(const float4*)(g_qk + (size_t)b * Fdim + c0);

    float4 acc = make_float4(0.f, 0.f, 0.f, 0.f);
    float m = -1e30f, s = 0.f;

    for (int t0 = 0; t0 < Tdim; t0 += ATC) {
        // 1) load this chunk: 8 independent coalesced LDG.128
        float4 v[ATC];
#pragma unroll
        for (int tc = 0; tc < ATC; tc++)
            v[tc] = *(const float4*)(Pb + (size_t)(t0 + tc) * Fdim + c0);

        // 2) score partials (this thread's 4 columns of each row)
        float p[ATC];
#pragma unroll
        for (int tc = 0; tc < ATC; tc++)
            p[tc] = v[tc].x * q4.x + v[tc].y * q4.y + v[tc].z * q4.z + v[tc].w * q4.w;

        // warp butterfly reduce all 8 partials
#pragma unroll
        for (int o = 16; o; o >>= 1)
#pragma unroll
            for (int tc = 0; tc < ATC; tc++)
                p[tc] += __shfl_xor_sync(0xffffffffu, p[tc], o);
        if (lane == 0) {
#pragma unroll
            for (int tc = 0; tc < ATC; tc++) scs[warp * ATC + tc] = p[tc];
        }
        __syncthreads();

        // 3) warp 0: cross-warp sum, chunk max, weights, weight sum
        if (warp == 0) {
            float sc = -1e30f;
            if (lane < ATC) {
                sc = 0.f;
#pragma unroll
                for (int w = 0; w < 8; w++) sc += scs[w * ATC + lane];
            }
            float cm = sc;
#pragma unroll
            for (int o = 16; o; o >>= 1) cm = fmaxf(cm, __shfl_xor_sync(0xffffffffu, cm, o));
            float nm = fmaxf(m, cm);
            float w = (lane < ATC) ? __expf(sc - nm) : 0.f;
            if (lane < ATC) wts[lane] = w;
            float sw = w;
#pragma unroll
            for (int o = 16; o; o >>= 1) sw += __shfl_xor_sync(0xffffffffu, sw, o);
            if (lane == 0) { bc[0] = nm; bc[1] = sw; }
        }
        __syncthreads();

        // 4) rescale + accumulate straight from registers
        float nm = bc[0];
        float c = __expf(m - nm);
        s = s * c + bc[1];
        m = nm;
        acc.x *= c; acc.y *= c; acc.z *= c; acc.w *= c;
#pragma unroll
        for (int tc = 0; tc < ATC; tc++) {
            float w = wts[tc];
            acc.x += w * v[tc].x; acc.y += w * v[tc].y;
            acc.z += w * v[tc].z; acc.w += w * v[tc].w;
        }
        // no barrier needed here: next chunk's writes to scs (lane0) precede
        // barrier A, and wts/bc are rewritten only after barrier A — by which
        // time every thread has finished this accumulate.
    }

    float inv = 1.f / s;
    float4 o = make_float4(acc.x * inv, acc.y * inv, acc.z * inv, acc.w * inv);
    __nv_bfloat16 h[4], l[4];
    split1(o.x, h[0], l[0]); split1(o.y, h[1], l[1]);
    split1(o.z, h[2], l[2]); split1(o.w, h[3], l[3]);
    size_t off = (size_t)b * Fdim + c0;
    *(uint2*)(g_ch + off) = *(uint2*)h;
    *(uint2*)(g_cl + off) = *(uint2*)l;
}

// ---------------------------------------------------------------------------
// kernel_launch
// ---------------------------------------------------------------------------
extern "C" void kernel_launch(void* const* d_in, const int* in_sizes, int n_in,
                              void* d_out, int out_size)
{
    const float* z  = (const float*)d_in[0];
    const float* P  = (const float*)d_in[1];
    const float* Wq = (const float*)d_in[2];
    const float* Wk = (const float*)d_in[3];
    const float* Wv = (const float*)d_in[4];
    const float* bq = (const float*)d_in[5];
    const float* bv = (const float*)d_in[7];
    float* out = (float*)d_out;

    float *qk;
    __nv_bfloat16 *zh, *zl, *qh, *ql, *ch, *cl, *wqh, *wql, *wkh, *wkl, *wvh, *wvl;
    cudaGetSymbolAddress((void**)&qk,  g_qk);
    cudaGetSymbolAddress((void**)&zh,  g_zh);  cudaGetSymbolAddress((void**)&zl,  g_zl);
    cudaGetSymbolAddress((void**)&qh,  g_qh);  cudaGetSymbolAddress((void**)&ql,  g_ql);
    cudaGetSymbolAddress((void**)&ch,  g_ch);  cudaGetSymbolAddress((void**)&cl,  g_cl);
    cudaGetSymbolAddress((void**)&wqh, g_wqh); cudaGetSymbolAddress((void**)&wql, g_wql);
    cudaGetSymbolAddress((void**)&wkh, g_wkh); cudaGetSymbolAddress((void**)&wkl, g_wkl);
    cudaGetSymbolAddress((void**)&wvh, g_wvh); cudaGetSymbolAddress((void**)&wvl, g_wvl);

    // ---- one fused split pass for z + all three weights ----
    cvt_split_all<<<1792, 256>>>(z, Wq, Wk, Wv);

    dim3 wg(Fdim / 32, Bdim / 64);        // 32 x 8 = 256 CTAs
    const int smNT = 4 * 9216 + 4 * (32 * 72 * 2);   // 55296
    const int smNN = 4 * 9216 + 4 * (64 * 40 * 2);   // 57344
    cudaFuncSetAttribute(wgemm_split<0, 1>, cudaFuncAttributeMaxDynamicSharedMemorySize, smNT);
    cudaFuncSetAttribute(wgemm_split<1, 0>, cudaFuncAttributeMaxDynamicSharedMemorySize, smNN);
    cudaFuncSetAttribute(wgemm_split<0, 2>, cudaFuncAttributeMaxDynamicSharedMemorySize, smNT);

    // ---- GEMM1: (qh,ql) = split(z @ Wq^T + bq)   [NT, EPI=split+bias] ----
    wgemm_split<0, 1><<<wg, 256, smNT>>>(zh, zl, wqh, wql, bq, nullptr, qh, ql, Bdim, Fdim, Fdim);

    // ---- GEMM2: qk = query @ Wk                  [NN, EPI=plain fp32] ----
    wgemm_split<1, 0><<<wg, 256, smNN>>>(qh, ql, wkh, wkl, nullptr, qk, nullptr, nullptr, Bdim, Fdim, Fdim);

    // ---- attention streaming pass (register-resident; writes ch/cl) ----
    attn_stream<<<Bdim, 256>>>(P);

    // ---- GEMM3: out = ctx @ Wv^T + bv            [NT, EPI=fp32+bias] ----
    wgemm_split<0, 2><<<wg, 256, smNT>>>(ch, cl, wvh, wvl, bv, out, nullptr, nullptr, Bdim, Fdim, Fdim);
}